// round 7
// baseline (speedup 1.0000x reference)
#include <cuda_runtime.h>
#include <cstddef>

#define NN 50000
#define NE 600000
#define DD 128
#define DC 32          // collapsed output width
#define NG 64

// -------- scratch (device globals; never passed as kernel args from host) --------
__device__ int   g_indeg[NN];
__device__ float g_dinv[NN];
__device__ int   g_rowptr[NN];
__device__ int   g_fill[NN];
__device__ int   g_total;
__device__ int   g_csr_src[NE];
__device__ float g_csr_norm[NE];
__device__ float g_u1[NN], g_u2[NN];
__device__ __align__(16) float g_M1[DD * DC];
__device__ __align__(16) float g_M2[DD * DC];
__device__ __align__(16) float g_M3[DD * DC];
__device__ __align__(16) float g_Wc[DD * DC];
__device__ float g_cv[4 * DC];
__device__ __align__(16) float g_Y0[(size_t)NN * DC];
__device__ __align__(16) float g_Y1[(size_t)NN * DC];
__device__ float g_pool[NG * DC];
__device__ float g_usum[NG * 3];
__device__ float g_cnt[NG];

// ======== prep ========
__global__ void k_zero() {
    int i = blockIdx.x * blockDim.x + threadIdx.x;
    if (i < NN) { g_indeg[i] = 0; g_fill[i] = 0; }
    if (i < NG * DC) g_pool[i] = 0.0f;
    if (i < NG * 3) g_usum[i] = 0.0f;
    if (i < NG) g_cnt[i] = 0.0f;
    if (i == 0) g_total = 0;
}

__global__ void k_count(const int* __restrict__ ei) {
    int e = blockIdx.x * blockDim.x + threadIdx.x;
    if (e >= NE) return;
    atomicAdd(&g_indeg[ei[NE + e]], 1);
}

// rowptr via atomic segment allocation (row order irrelevant for a sum),
// fused with dinv and per-graph node counts.
__global__ void k_alloc(const int* __restrict__ batch) {
    int n = blockIdx.x * blockDim.x + threadIdx.x;
    if (n >= NN) return;
    int d = g_indeg[n];
    g_rowptr[n] = atomicAdd(&g_total, d);
    g_dinv[n]   = rsqrtf((float)d + 1.0f);
    atomicAdd(&g_cnt[batch[n]], 1.0f);
}

__global__ void k_fill(const int* __restrict__ ei) {
    int e = blockIdx.x * blockDim.x + threadIdx.x;
    if (e >= NE) return;
    int s = ei[e];
    int d = ei[NE + e];
    int pos = g_rowptr[d] + atomicAdd(&g_fill[d], 1);
    g_csr_src[pos]  = s;
    g_csr_norm[pos] = g_dinv[s] * g_dinv[d];
}

// ======== weight chain: C[128,32] = A[128,128] @ B[128,32] ========
// bsel: 0 = Bext (fcW), 1 = g_M3, 2 = g_M2, 3 = g_M1
// csel: 0 = g_M3, 1 = g_M2, 2 = g_M1, 3 = g_Wc
__global__ void k_mm(const float* __restrict__ A, const float* __restrict__ Bext,
                     int bsel, int csel) {
    const float* B = (bsel == 0) ? Bext : (bsel == 1) ? g_M3 : (bsel == 2) ? g_M2 : g_M1;
    float*       C = (csel == 0) ? g_M3 : (csel == 1) ? g_M2 : (csel == 2) ? g_M1 : g_Wc;
    int t = blockIdx.x * blockDim.x + threadIdx.x;
    int r = t >> 5, c = t & 31;
    float s = 0.0f;
#pragma unroll 8
    for (int k = 0; k < DD; k++) s += A[r * DD + k] * B[k * DC + c];
    C[r * DC + c] = s;
}

// c_i = b_i^T M_i  (M4 = fcW)
__global__ void k_cvec(const float* __restrict__ b1, const float* __restrict__ b2,
                       const float* __restrict__ b3, const float* __restrict__ b4,
                       const float* __restrict__ fcW) {
    int t = threadIdx.x;              // 128 threads
    int i = t >> 5, c = t & 31;
    const float* b = (i == 0) ? b1 : (i == 1) ? b2 : (i == 2) ? b3 : b4;
    const float* M = (i == 0) ? g_M1 : (i == 1) ? g_M2 : (i == 2) ? g_M3 : fcW;
    float s = 0.0f;
#pragma unroll 8
    for (int k = 0; k < DD; k++) s += b[k] * M[k * DC + c];
    g_cv[i * DC + c] = s;
}

// ======== Y0 = X @ Wc   (X:[NN,128], Wc:[128,32]) ========
__global__ __launch_bounds__(256) void k_gemmY(const float* __restrict__ X) {
    __shared__ float Ws[DD][DC];
    __shared__ float As[128][33];
    int t  = threadIdx.x;
    int m0 = blockIdx.x * 128;
    int rb = t >> 3;                  // 0..31
    int cg = (t & 7) << 2;            // col group of 4

#pragma unroll
    for (int i = 0; i < 4; i++) {
        int lin = t + i * 256;
        int r = lin >> 3, c4 = (lin & 7) << 2;
        *(float4*)&Ws[r][c4] = *(const float4*)(g_Wc + r * DC + c4);
    }

    float4 ac[4];
#pragma unroll
    for (int j = 0; j < 4; j++) ac[j] = make_float4(0.f, 0.f, 0.f, 0.f);

    for (int k0 = 0; k0 < DD; k0 += 32) {
        __syncthreads();
#pragma unroll
        for (int i = 0; i < 4; i++) {
            int lin = t + i * 256;
            int r = lin >> 3, c4 = (lin & 7) << 2;
            int gr = m0 + r;
            float4 v = make_float4(0.f, 0.f, 0.f, 0.f);
            if (gr < NN) v = *(const float4*)(X + (size_t)gr * DD + k0 + c4);
            As[r][c4 + 0] = v.x; As[r][c4 + 1] = v.y;
            As[r][c4 + 2] = v.z; As[r][c4 + 3] = v.w;
        }
        __syncthreads();
#pragma unroll
        for (int k = 0; k < 32; k++) {
            float4 wv = *(const float4*)&Ws[k0 + k][cg];
#pragma unroll
            for (int j = 0; j < 4; j++) {
                float a = As[rb + 32 * j][k];
                ac[j].x += a * wv.x; ac[j].y += a * wv.y;
                ac[j].z += a * wv.z; ac[j].w += a * wv.w;
            }
        }
    }

#pragma unroll
    for (int j = 0; j < 4; j++) {
        int gr = m0 + rb + 32 * j;
        if (gr < NN) *(float4*)(g_Y0 + (size_t)gr * DC + cg) = ac[j];
    }
}

// ======== fused aggregate: Y' = Â Y, plus the scalar u-chain on lane 0,
//          plus pooled sums folded in (usum in stages 1-3, pool in stage 4) ====
// STAGE 1: Y0->Y1, 1 ->u1 (store + usum[0])
// STAGE 2: Y1->Y0, u1->u2 (store + usum[1])
// STAGE 3: Y0->Y1, u2->u3 (usum[2] only)
// STAGE 4: Y1 -> g_pool directly (no Y store)
template <int STAGE>
__global__ __launch_bounds__(256) void k_vagg(const int* __restrict__ batch) {
    const float* Yin = (STAGE == 1 || STAGE == 3) ? g_Y0 : g_Y1;
    float*      Yout = (STAGE == 1 || STAGE == 3) ? g_Y1 : g_Y0;
    const float* uin = (STAGE == 2) ? g_u1 : (STAGE == 3) ? g_u2 : nullptr;
    float*      uout = (STAGE == 1) ? g_u1 : (STAGE == 2) ? g_u2 : nullptr;

    int gid = blockIdx.x * blockDim.x + threadIdx.x;
    int n   = gid >> 5;
    if (n >= NN) return;
    int l = gid & 31;

    float dv = g_dinv[n];
    float sn = dv * dv;
    float accv = sn * Yin[(size_t)n * DC + l];
    float accu = 0.0f;
    if (STAGE == 1) accu = sn;
    else if (STAGE == 2 || STAGE == 3) accu = sn * uin[n];

    int beg = g_rowptr[n], end = beg + g_indeg[n];
    int e = beg;
    for (; e + 4 <= end; e += 4) {
        int   s0 = g_csr_src[e],      s1 = g_csr_src[e + 1];
        int   s2 = g_csr_src[e + 2],  s3 = g_csr_src[e + 3];
        float w0 = g_csr_norm[e],     w1 = g_csr_norm[e + 1];
        float w2 = g_csr_norm[e + 2], w3 = g_csr_norm[e + 3];
        accv += w0 * Yin[(size_t)s0 * DC + l] + w1 * Yin[(size_t)s1 * DC + l]
              + w2 * Yin[(size_t)s2 * DC + l] + w3 * Yin[(size_t)s3 * DC + l];
        if (STAGE < 4 && l == 0) {
            if (STAGE == 1) accu += w0 + w1 + w2 + w3;
            else accu += w0 * uin[s0] + w1 * uin[s1] + w2 * uin[s2] + w3 * uin[s3];
        }
    }
    for (; e < end; e++) {
        int   s0 = g_csr_src[e];
        float w0 = g_csr_norm[e];
        accv += w0 * Yin[(size_t)s0 * DC + l];
        if (STAGE < 4 && l == 0)
            accu += (STAGE == 1) ? w0 : w0 * uin[s0];
    }

    if (STAGE < 4) {
        Yout[(size_t)n * DC + l] = accv;
        if (l == 0) {
            if (STAGE < 3) uout[n] = accu;
            atomicAdd(&g_usum[batch[n] * 3 + (STAGE - 1)], accu);
        }
    } else {
        atomicAdd(&g_pool[batch[n] * DC + l], accv);
    }
}

// ======== final: mean pool + rank-1 bias terms ========
__global__ void k_final(const float* __restrict__ fcb, float* __restrict__ out) {
    int g = blockIdx.x;
    int c = threadIdx.x;   // 32
    float cnt = g_cnt[g];
    float v = g_pool[g * DC + c]
            + g_usum[g * 3 + 2] * g_cv[0 * DC + c]      // u3 * (b1ᵀ W2W3W4 fcW)
            + g_usum[g * 3 + 1] * g_cv[1 * DC + c]      // u2 * (b2ᵀ W3W4 fcW)
            + g_usum[g * 3 + 0] * g_cv[2 * DC + c]      // u1 * (b3ᵀ W4 fcW)
            + cnt * (g_cv[3 * DC + c] + fcb[c]);        // 1  * (b4ᵀ fcW + fcb)
    out[g * DC + c] = v / fmaxf(cnt, 1.0f);
}

extern "C" void kernel_launch(void* const* d_in, const int* in_sizes, int n_in,
                              void* d_out, int out_size) {
    const float* x     = (const float*)d_in[0];
    const int*   ei    = (const int*)d_in[1];
    const int*   batch = (const int*)d_in[2];
    const float* W1 = (const float*)d_in[3];
    const float* b1 = (const float*)d_in[4];
    const float* W2 = (const float*)d_in[5];
    const float* b2 = (const float*)d_in[6];
    const float* W3 = (const float*)d_in[7];
    const float* b3 = (const float*)d_in[8];
    const float* W4 = (const float*)d_in[9];
    const float* b4 = (const float*)d_in[10];
    const float* fcW = (const float*)d_in[11];
    const float* fcb = (const float*)d_in[12];
    float* out = (float*)d_out;

    const int TB = 256;
    // CSR prep (scan-free)
    k_zero <<<(NN + TB - 1) / TB, TB>>>();
    k_count<<<(NE + TB - 1) / TB, TB>>>(ei);
    k_alloc<<<(NN + TB - 1) / TB, TB>>>(batch);
    k_fill <<<(NE + TB - 1) / TB, TB>>>(ei);

    // weight chain: M3 = W4 fcW; M2 = W3 M3; M1 = W2 M2; Wc = W1 M1
    k_mm<<<16, TB>>>(W4, fcW, 0, 0);
    k_mm<<<16, TB>>>(W3, nullptr, 1, 1);
    k_mm<<<16, TB>>>(W2, nullptr, 2, 2);
    k_mm<<<16, TB>>>(W1, nullptr, 3, 3);
    k_cvec<<<1, 128>>>(b1, b2, b3, b4, fcW);

    // Y0 = X @ Wc
    k_gemmY<<<(NN + 127) / 128, TB>>>(x);

    // fused Â-powers (+u chain, +pool folds)
    const int AGG_BLOCKS = (NN * 32 + TB - 1) / TB;   // 6250
    k_vagg<1><<<AGG_BLOCKS, TB>>>(batch);
    k_vagg<2><<<AGG_BLOCKS, TB>>>(batch);
    k_vagg<3><<<AGG_BLOCKS, TB>>>(batch);
    k_vagg<4><<<AGG_BLOCKS, TB>>>(batch);

    k_final<<<NG, DC>>>(fcb, out);
}

// round 8
// speedup vs baseline: 1.0026x; 1.0026x over previous
#include <cuda_runtime.h>
#include <cstddef>

#define NN 50000
#define NE 600000
#define DD 128
#define DC 32          // collapsed output width
#define NG 64

// -------- scratch (device globals; never passed as kernel args from host) --------
__device__ int   g_indeg[NN];
__device__ float g_dinv[NN];
__device__ int   g_rowptr[NN];
__device__ int   g_fill[NN];
__device__ int   g_total;
__device__ int   g_csr_src[NE];
__device__ float g_csr_norm[NE];
__device__ float g_u1[NN], g_u2[NN];
__device__ __align__(16) float g_M1[DD * DC];
__device__ __align__(16) float g_M2[DD * DC];
__device__ __align__(16) float g_M3[DD * DC];
__device__ __align__(16) float g_Wc[DD * DC];
__device__ float g_cv[4 * DC];
__device__ __align__(16) float g_Y0[(size_t)NN * DC];
__device__ __align__(16) float g_Y1[(size_t)NN * DC];
__device__ float g_pool[NG * DC];
__device__ float g_usum[NG * 3];
__device__ float g_cnt[NG];

// ======== prep ========
__global__ void k_zero() {
    int i = blockIdx.x * blockDim.x + threadIdx.x;
    if (i < NN) { g_indeg[i] = 0; g_fill[i] = 0; }
    if (i < NG * DC) g_pool[i] = 0.0f;
    if (i < NG * 3) g_usum[i] = 0.0f;
    if (i < NG) g_cnt[i] = 0.0f;
    if (i == 0) g_total = 0;
}

__global__ void k_count(const int* __restrict__ ei) {
    int e = blockIdx.x * blockDim.x + threadIdx.x;
    if (e >= NE) return;
    atomicAdd(&g_indeg[ei[NE + e]], 1);
}

// rowptr via atomic segment allocation (row order irrelevant for a sum),
// fused with dinv and per-graph node counts.
__global__ void k_alloc(const int* __restrict__ batch) {
    int n = blockIdx.x * blockDim.x + threadIdx.x;
    if (n >= NN) return;
    int d = g_indeg[n];
    g_rowptr[n] = atomicAdd(&g_total, d);
    g_dinv[n]   = rsqrtf((float)d + 1.0f);
    atomicAdd(&g_cnt[batch[n]], 1.0f);
}

__global__ void k_fill(const int* __restrict__ ei) {
    int e = blockIdx.x * blockDim.x + threadIdx.x;
    if (e >= NE) return;
    int s = ei[e];
    int d = ei[NE + e];
    int pos = g_rowptr[d] + atomicAdd(&g_fill[d], 1);
    g_csr_src[pos]  = s;
    g_csr_norm[pos] = g_dinv[s] * g_dinv[d];
}

// ======== weight chain: C[128,32] = A[128,128] @ B[128,32] ========
// bsel: 0 = Bext (fcW), 1 = g_M3, 2 = g_M2, 3 = g_M1
// csel: 0 = g_M3, 1 = g_M2, 2 = g_M1, 3 = g_Wc
__global__ void k_mm(const float* __restrict__ A, const float* __restrict__ Bext,
                     int bsel, int csel) {
    const float* B = (bsel == 0) ? Bext : (bsel == 1) ? g_M3 : (bsel == 2) ? g_M2 : g_M1;
    float*       C = (csel == 0) ? g_M3 : (csel == 1) ? g_M2 : (csel == 2) ? g_M1 : g_Wc;
    int t = blockIdx.x * blockDim.x + threadIdx.x;
    int r = t >> 5, c = t & 31;
    float s = 0.0f;
#pragma unroll 8
    for (int k = 0; k < DD; k++) s += A[r * DD + k] * B[k * DC + c];
    C[r * DC + c] = s;
}

// c_i = b_i^T M_i  (M4 = fcW)
__global__ void k_cvec(const float* __restrict__ b1, const float* __restrict__ b2,
                       const float* __restrict__ b3, const float* __restrict__ b4,
                       const float* __restrict__ fcW) {
    int t = threadIdx.x;              // 128 threads
    int i = t >> 5, c = t & 31;
    const float* b = (i == 0) ? b1 : (i == 1) ? b2 : (i == 2) ? b3 : b4;
    const float* M = (i == 0) ? g_M1 : (i == 1) ? g_M2 : (i == 2) ? g_M3 : fcW;
    float s = 0.0f;
#pragma unroll 8
    for (int k = 0; k < DD; k++) s += b[k] * M[k * DC + c];
    g_cv[i * DC + c] = s;
}

// ======== Y0 = X @ Wc   (X:[NN,128], Wc:[128,32]) ========
__global__ __launch_bounds__(256) void k_gemmY(const float* __restrict__ X) {
    __shared__ float Ws[DD][DC];
    __shared__ float As[128][33];
    int t  = threadIdx.x;
    int m0 = blockIdx.x * 128;
    int rb = t >> 3;                  // 0..31
    int cg = (t & 7) << 2;            // col group of 4

#pragma unroll
    for (int i = 0; i < 4; i++) {
        int lin = t + i * 256;
        int r = lin >> 3, c4 = (lin & 7) << 2;
        *(float4*)&Ws[r][c4] = *(const float4*)(g_Wc + r * DC + c4);
    }

    float4 ac[4];
#pragma unroll
    for (int j = 0; j < 4; j++) ac[j] = make_float4(0.f, 0.f, 0.f, 0.f);

    for (int k0 = 0; k0 < DD; k0 += 32) {
        __syncthreads();
#pragma unroll
        for (int i = 0; i < 4; i++) {
            int lin = t + i * 256;
            int r = lin >> 3, c4 = (lin & 7) << 2;
            int gr = m0 + r;
            float4 v = make_float4(0.f, 0.f, 0.f, 0.f);
            if (gr < NN) v = *(const float4*)(X + (size_t)gr * DD + k0 + c4);
            As[r][c4 + 0] = v.x; As[r][c4 + 1] = v.y;
            As[r][c4 + 2] = v.z; As[r][c4 + 3] = v.w;
        }
        __syncthreads();
#pragma unroll
        for (int k = 0; k < 32; k++) {
            float4 wv = *(const float4*)&Ws[k0 + k][cg];
#pragma unroll
            for (int j = 0; j < 4; j++) {
                float a = As[rb + 32 * j][k];
                ac[j].x += a * wv.x; ac[j].y += a * wv.y;
                ac[j].z += a * wv.z; ac[j].w += a * wv.w;
            }
        }
    }

#pragma unroll
    for (int j = 0; j < 4; j++) {
        int gr = m0 + rb + 32 * j;
        if (gr < NN) *(float4*)(g_Y0 + (size_t)gr * DC + cg) = ac[j];
    }
}

// ======== fused aggregate: Y' = Â Y, plus the scalar u-chain on lane 0,
//          plus pooled sums folded in (usum in stages 1-3, pool in stage 4) ====
// STAGE 1: Y0->Y1, 1 ->u1 (store + usum[0])
// STAGE 2: Y1->Y0, u1->u2 (store + usum[1])
// STAGE 3: Y0->Y1, u2->u3 (usum[2] only)
// STAGE 4: Y1 -> g_pool directly (no Y store)
template <int STAGE>
__global__ __launch_bounds__(256) void k_vagg(const int* __restrict__ batch) {
    const float* Yin = (STAGE == 1 || STAGE == 3) ? g_Y0 : g_Y1;
    float*      Yout = (STAGE == 1 || STAGE == 3) ? g_Y1 : g_Y0;
    const float* uin = (STAGE == 2) ? g_u1 : (STAGE == 3) ? g_u2 : nullptr;
    float*      uout = (STAGE == 1) ? g_u1 : (STAGE == 2) ? g_u2 : nullptr;

    int gid = blockIdx.x * blockDim.x + threadIdx.x;
    int n   = gid >> 5;
    if (n >= NN) return;
    int l = gid & 31;

    float dv = g_dinv[n];
    float sn = dv * dv;
    float accv = sn * Yin[(size_t)n * DC + l];
    float accu = 0.0f;
    if (STAGE == 1) accu = sn;
    else if (STAGE == 2 || STAGE == 3) accu = sn * uin[n];

    int beg = g_rowptr[n], end = beg + g_indeg[n];
    int e = beg;
    for (; e + 4 <= end; e += 4) {
        int   s0 = g_csr_src[e],      s1 = g_csr_src[e + 1];
        int   s2 = g_csr_src[e + 2],  s3 = g_csr_src[e + 3];
        float w0 = g_csr_norm[e],     w1 = g_csr_norm[e + 1];
        float w2 = g_csr_norm[e + 2], w3 = g_csr_norm[e + 3];
        accv += w0 * Yin[(size_t)s0 * DC + l] + w1 * Yin[(size_t)s1 * DC + l]
              + w2 * Yin[(size_t)s2 * DC + l] + w3 * Yin[(size_t)s3 * DC + l];
        if (STAGE < 4 && l == 0) {
            if (STAGE == 1) accu += w0 + w1 + w2 + w3;
            else accu += w0 * uin[s0] + w1 * uin[s1] + w2 * uin[s2] + w3 * uin[s3];
        }
    }
    for (; e < end; e++) {
        int   s0 = g_csr_src[e];
        float w0 = g_csr_norm[e];
        accv += w0 * Yin[(size_t)s0 * DC + l];
        if (STAGE < 4 && l == 0)
            accu += (STAGE == 1) ? w0 : w0 * uin[s0];
    }

    if (STAGE < 4) {
        Yout[(size_t)n * DC + l] = accv;
        if (l == 0) {
            if (STAGE < 3) uout[n] = accu;
            atomicAdd(&g_usum[batch[n] * 3 + (STAGE - 1)], accu);
        }
    } else {
        atomicAdd(&g_pool[batch[n] * DC + l], accv);
    }
}

// ======== final: mean pool + rank-1 bias terms ========
__global__ void k_final(const float* __restrict__ fcb, float* __restrict__ out) {
    int g = blockIdx.x;
    int c = threadIdx.x;   // 32
    float cnt = g_cnt[g];
    float v = g_pool[g * DC + c]
            + g_usum[g * 3 + 2] * g_cv[0 * DC + c]      // u3 * (b1ᵀ W2W3W4 fcW)
            + g_usum[g * 3 + 1] * g_cv[1 * DC + c]      // u2 * (b2ᵀ W3W4 fcW)
            + g_usum[g * 3 + 0] * g_cv[2 * DC + c]      // u1 * (b3ᵀ W4 fcW)
            + cnt * (g_cv[3 * DC + c] + fcb[c]);        // 1  * (b4ᵀ fcW + fcb)
    out[g * DC + c] = v / fmaxf(cnt, 1.0f);
}

extern "C" void kernel_launch(void* const* d_in, const int* in_sizes, int n_in,
                              void* d_out, int out_size) {
    const float* x     = (const float*)d_in[0];
    const int*   ei    = (const int*)d_in[1];
    const int*   batch = (const int*)d_in[2];
    const float* W1 = (const float*)d_in[3];
    const float* b1 = (const float*)d_in[4];
    const float* W2 = (const float*)d_in[5];
    const float* b2 = (const float*)d_in[6];
    const float* W3 = (const float*)d_in[7];
    const float* b3 = (const float*)d_in[8];
    const float* W4 = (const float*)d_in[9];
    const float* b4 = (const float*)d_in[10];
    const float* fcW = (const float*)d_in[11];
    const float* fcb = (const float*)d_in[12];
    float* out = (float*)d_out;

    const int TB = 256;
    // CSR prep (scan-free)
    k_zero <<<(NN + TB - 1) / TB, TB>>>();
    k_count<<<(NE + TB - 1) / TB, TB>>>(ei);
    k_alloc<<<(NN + TB - 1) / TB, TB>>>(batch);
    k_fill <<<(NE + TB - 1) / TB, TB>>>(ei);

    // weight chain: M3 = W4 fcW; M2 = W3 M3; M1 = W2 M2; Wc = W1 M1
    k_mm<<<16, TB>>>(W4, fcW, 0, 0);
    k_mm<<<16, TB>>>(W3, nullptr, 1, 1);
    k_mm<<<16, TB>>>(W2, nullptr, 2, 2);
    k_mm<<<16, TB>>>(W1, nullptr, 3, 3);
    k_cvec<<<1, 128>>>(b1, b2, b3, b4, fcW);

    // Y0 = X @ Wc
    k_gemmY<<<(NN + 127) / 128, TB>>>(x);

    // fused Â-powers (+u chain, +pool folds)
    const int AGG_BLOCKS = (NN * 32 + TB - 1) / TB;   // 6250
    k_vagg<1><<<AGG_BLOCKS, TB>>>(batch);
    k_vagg<2><<<AGG_BLOCKS, TB>>>(batch);
    k_vagg<3><<<AGG_BLOCKS, TB>>>(batch);
    k_vagg<4><<<AGG_BLOCKS, TB>>>(batch);

    k_final<<<NG, DC>>>(fcb, out);
}

// round 9
// speedup vs baseline: 1.1143x; 1.1114x over previous
#include <cuda_runtime.h>
#include <cstddef>

#define NN 50000
#define NE 600000
#define DD 128
#define DC 32          // collapsed output width
#define NG 64

// -------- scratch (device globals; never passed as kernel args from host) --------
__device__ int   g_indeg[NN];
__device__ float g_dinv[NN];
__device__ int   g_rowptr[NN];
__device__ int   g_fill[NN];
__device__ int   g_total;
__device__ __align__(8) int2 g_csr[NE];    // (src, __float_as_int(norm))
__device__ float g_u1[NN], g_u2[NN];
__device__ __align__(16) float g_M1[DD * DC];
__device__ __align__(16) float g_M2[DD * DC];
__device__ __align__(16) float g_M3[DD * DC];
__device__ __align__(16) float g_Wc[DD * DC];
__device__ float g_cv[4 * DC];
__device__ __align__(16) float g_Y0[(size_t)NN * DC];
__device__ __align__(16) float g_Y1[(size_t)NN * DC];
__device__ float g_pool[NG * DC];
__device__ float g_usum[NG * 3];
__device__ float g_cnt[NG];

// ======== prep ========
__global__ void k_zero() {
    int i = blockIdx.x * blockDim.x + threadIdx.x;
    if (i < NN) { g_indeg[i] = 0; g_fill[i] = 0; }
    if (i < NG * DC) g_pool[i] = 0.0f;
    if (i < NG * 3) g_usum[i] = 0.0f;
    if (i < NG) g_cnt[i] = 0.0f;
    if (i == 0) g_total = 0;
}

__global__ void k_count(const int* __restrict__ ei) {
    int e = blockIdx.x * blockDim.x + threadIdx.x;
    if (e >= NE) return;
    atomicAdd(&g_indeg[ei[NE + e]], 1);
}

// rowptr via atomic segment allocation (row order irrelevant for a sum),
// fused with dinv and per-graph node counts.
__global__ void k_alloc(const int* __restrict__ batch) {
    int n = blockIdx.x * blockDim.x + threadIdx.x;
    if (n >= NN) return;
    int d = g_indeg[n];
    g_rowptr[n] = atomicAdd(&g_total, d);
    g_dinv[n]   = rsqrtf((float)d + 1.0f);
    atomicAdd(&g_cnt[batch[n]], 1.0f);
}

__global__ void k_fill(const int* __restrict__ ei) {
    int e = blockIdx.x * blockDim.x + threadIdx.x;
    if (e >= NE) return;
    int s = ei[e];
    int d = ei[NE + e];
    int pos = g_rowptr[d] + atomicAdd(&g_fill[d], 1);
    g_csr[pos] = make_int2(s, __float_as_int(g_dinv[s] * g_dinv[d]));
}

// ======== weight chain: C[128,32] = A[128,128] @ B[128,32] ========
// bsel: 0 = Bext (fcW), 1 = g_M3, 2 = g_M2, 3 = g_M1
// csel: 0 = g_M3, 1 = g_M2, 2 = g_M1, 3 = g_Wc
__global__ void k_mm(const float* __restrict__ A, const float* __restrict__ Bext,
                     int bsel, int csel) {
    const float* B = (bsel == 0) ? Bext : (bsel == 1) ? g_M3 : (bsel == 2) ? g_M2 : g_M1;
    float*       C = (csel == 0) ? g_M3 : (csel == 1) ? g_M2 : (csel == 2) ? g_M1 : g_Wc;
    int t = blockIdx.x * blockDim.x + threadIdx.x;
    int r = t >> 5, c = t & 31;
    float s = 0.0f;
#pragma unroll 8
    for (int k = 0; k < DD; k++) s += A[r * DD + k] * B[k * DC + c];
    C[r * DC + c] = s;
}

// c_i = b_i^T M_i  (M4 = fcW)
__global__ void k_cvec(const float* __restrict__ b1, const float* __restrict__ b2,
                       const float* __restrict__ b3, const float* __restrict__ b4,
                       const float* __restrict__ fcW) {
    int t = threadIdx.x;              // 128 threads
    int i = t >> 5, c = t & 31;
    const float* b = (i == 0) ? b1 : (i == 1) ? b2 : (i == 2) ? b3 : b4;
    const float* M = (i == 0) ? g_M1 : (i == 1) ? g_M2 : (i == 2) ? g_M3 : fcW;
    float s = 0.0f;
#pragma unroll 8
    for (int k = 0; k < DD; k++) s += b[k] * M[k * DC + c];
    g_cv[i * DC + c] = s;
}

// ======== Y0 = X @ Wc   (X:[NN,128], Wc:[128,32]) ========
__global__ __launch_bounds__(256) void k_gemmY(const float* __restrict__ X) {
    __shared__ float Ws[DD][DC];
    __shared__ float As[128][33];
    int t  = threadIdx.x;
    int m0 = blockIdx.x * 128;
    int rb = t >> 3;                  // 0..31
    int cg = (t & 7) << 2;            // col group of 4

#pragma unroll
    for (int i = 0; i < 4; i++) {
        int lin = t + i * 256;
        int r = lin >> 3, c4 = (lin & 7) << 2;
        *(float4*)&Ws[r][c4] = *(const float4*)(g_Wc + r * DC + c4);
    }

    float4 ac[4];
#pragma unroll
    for (int j = 0; j < 4; j++) ac[j] = make_float4(0.f, 0.f, 0.f, 0.f);

    for (int k0 = 0; k0 < DD; k0 += 32) {
        __syncthreads();
#pragma unroll
        for (int i = 0; i < 4; i++) {
            int lin = t + i * 256;
            int r = lin >> 3, c4 = (lin & 7) << 2;
            int gr = m0 + r;
            float4 v = make_float4(0.f, 0.f, 0.f, 0.f);
            if (gr < NN) v = *(const float4*)(X + (size_t)gr * DD + k0 + c4);
            As[r][c4 + 0] = v.x; As[r][c4 + 1] = v.y;
            As[r][c4 + 2] = v.z; As[r][c4 + 3] = v.w;
        }
        __syncthreads();
#pragma unroll
        for (int k = 0; k < 32; k++) {
            float4 wv = *(const float4*)&Ws[k0 + k][cg];
#pragma unroll
            for (int j = 0; j < 4; j++) {
                float a = As[rb + 32 * j][k];
                ac[j].x += a * wv.x; ac[j].y += a * wv.y;
                ac[j].z += a * wv.z; ac[j].w += a * wv.w;
            }
        }
    }

#pragma unroll
    for (int j = 0; j < 4; j++) {
        int gr = m0 + rb + 32 * j;
        if (gr < NN) *(float4*)(g_Y0 + (size_t)gr * DC + cg) = ac[j];
    }
}

// ======== scalar aggregate: u' = Â u, usum atomic folded at end ========
// stage 0: ones -> u1 ; stage 1: u1 -> u2 ; stage 2: u2 -> usum only
__global__ void k_uagg(const int* __restrict__ batch, int stage) {
    int n = blockIdx.x * blockDim.x + threadIdx.x;
    if (n >= NN) return;
    const float* uin = (stage == 1) ? g_u1 : (stage == 2) ? g_u2 : nullptr;
    float dv = g_dinv[n];
    float acc = (stage == 0) ? dv * dv : dv * dv * uin[n];
    int beg = g_rowptr[n], end = beg + g_indeg[n];
    if (stage == 0) {
        for (int e = beg; e < end; e++) acc += __int_as_float(g_csr[e].y);
    } else {
        for (int e = beg; e < end; e++) {
            int2 cv = g_csr[e];
            acc += __int_as_float(cv.y) * uin[cv.x];
        }
    }
    if (stage == 0)      g_u1[n] = acc;
    else if (stage == 1) g_u2[n] = acc;
    atomicAdd(&g_usum[batch[n] * 3 + stage], acc);
}

// ======== vector aggregate (D=32): Yout = Â Yin; stage 4 pools directly ========
// STAGE 1: Y0->Y1   STAGE 2: Y1->Y0   STAGE 3: Y0->Y1   STAGE 4: Y1->g_pool
template <int STAGE>
__global__ __launch_bounds__(256) void k_vagg(const int* __restrict__ batch) {
    const float* __restrict__ Yin = (STAGE == 1 || STAGE == 3) ? g_Y0 : g_Y1;
    float*       __restrict__ Yout = (STAGE == 1 || STAGE == 3) ? g_Y1 : g_Y0;

    int gid = blockIdx.x * blockDim.x + threadIdx.x;
    int n   = gid >> 5;
    if (n >= NN) return;
    int l = gid & 31;

    float dv  = g_dinv[n];
    float acc = dv * dv * Yin[(size_t)n * DC + l];

    int beg = g_rowptr[n], end = beg + g_indeg[n];
    int e = beg;
    for (; e + 4 <= end; e += 4) {
        int2 c0 = g_csr[e],     c1 = g_csr[e + 1];
        int2 c2 = g_csr[e + 2], c3 = g_csr[e + 3];
        acc += __int_as_float(c0.y) * Yin[(size_t)c0.x * DC + l]
             + __int_as_float(c1.y) * Yin[(size_t)c1.x * DC + l]
             + __int_as_float(c2.y) * Yin[(size_t)c2.x * DC + l]
             + __int_as_float(c3.y) * Yin[(size_t)c3.x * DC + l];
    }
    for (; e < end; e++) {
        int2 cv = g_csr[e];
        acc += __int_as_float(cv.y) * Yin[(size_t)cv.x * DC + l];
    }

    if (STAGE < 4)
        Yout[(size_t)n * DC + l] = acc;
    else
        atomicAdd(&g_pool[batch[n] * DC + l], acc);
}

// ======== final: mean pool + rank-1 bias terms ========
__global__ void k_final(const float* __restrict__ fcb, float* __restrict__ out) {
    int g = blockIdx.x;
    int c = threadIdx.x;   // 32
    float cnt = g_cnt[g];
    float v = g_pool[g * DC + c]
            + g_usum[g * 3 + 2] * g_cv[0 * DC + c]      // u3 * (b1ᵀ W2W3W4 fcW)
            + g_usum[g * 3 + 1] * g_cv[1 * DC + c]      // u2 * (b2ᵀ W3W4 fcW)
            + g_usum[g * 3 + 0] * g_cv[2 * DC + c]      // u1 * (b3ᵀ W4 fcW)
            + cnt * (g_cv[3 * DC + c] + fcb[c]);        // 1  * (b4ᵀ fcW + fcb)
    out[g * DC + c] = v / fmaxf(cnt, 1.0f);
}

extern "C" void kernel_launch(void* const* d_in, const int* in_sizes, int n_in,
                              void* d_out, int out_size) {
    const float* x     = (const float*)d_in[0];
    const int*   ei    = (const int*)d_in[1];
    const int*   batch = (const int*)d_in[2];
    const float* W1 = (const float*)d_in[3];
    const float* b1 = (const float*)d_in[4];
    const float* W2 = (const float*)d_in[5];
    const float* b2 = (const float*)d_in[6];
    const float* W3 = (const float*)d_in[7];
    const float* b3 = (const float*)d_in[8];
    const float* W4 = (const float*)d_in[9];
    const float* b4 = (const float*)d_in[10];
    const float* fcW = (const float*)d_in[11];
    const float* fcb = (const float*)d_in[12];
    float* out = (float*)d_out;

    const int TB = 256;
    // CSR prep (scan-free)
    k_zero <<<(NN + TB - 1) / TB, TB>>>();
    k_count<<<(NE + TB - 1) / TB, TB>>>(ei);
    k_alloc<<<(NN + TB - 1) / TB, TB>>>(batch);
    k_fill <<<(NE + TB - 1) / TB, TB>>>(ei);

    // weight chain: M3 = W4 fcW; M2 = W3 M3; M1 = W2 M2; Wc = W1 M1
    k_mm<<<16, TB>>>(W4, fcW, 0, 0);
    k_mm<<<16, TB>>>(W3, nullptr, 1, 1);
    k_mm<<<16, TB>>>(W2, nullptr, 2, 2);
    k_mm<<<16, TB>>>(W1, nullptr, 3, 3);
    k_cvec<<<1, 128>>>(b1, b2, b3, b4, fcW);

    // Y0 = X @ Wc
    k_gemmY<<<(NN + 127) / 128, TB>>>(x);

    // u_k = Â^k 1  (clean standalone kernels; usum folded at end)
    k_uagg<<<(NN + TB - 1) / TB, TB>>>(batch, 0);
    k_uagg<<<(NN + TB - 1) / TB, TB>>>(batch, 1);
    k_uagg<<<(NN + TB - 1) / TB, TB>>>(batch, 2);

    // Â^4 Y0 with clean inner loops; stage 4 pools directly
    const int AGG_BLOCKS = (NN * 32 + TB - 1) / TB;   // 6250
    k_vagg<1><<<AGG_BLOCKS, TB>>>(batch);
    k_vagg<2><<<AGG_BLOCKS, TB>>>(batch);
    k_vagg<3><<<AGG_BLOCKS, TB>>>(batch);
    k_vagg<4><<<AGG_BLOCKS, TB>>>(batch);

    k_final<<<NG, DC>>>(fcb, out);
}

// round 10
// speedup vs baseline: 1.2710x; 1.1406x over previous
#include <cuda_runtime.h>
#include <cstddef>

#define NN 50000
#define NE 600000
#define DD 128
#define DC 32          // collapsed output width
#define NG 64

#define SCAN_BS 256
#define SCAN_NB ((NN + SCAN_BS - 1) / SCAN_BS)   // 196

// -------- scratch (device globals; never passed as kernel args from host) --------
__device__ int   g_indeg[NN];
__device__ float g_dinv[NN];
__device__ int   g_rowptr[NN];
__device__ int   g_fill[NN];
__device__ int   g_scan_tmp[NN];
__device__ int   g_bsum[SCAN_NB];
__device__ __align__(8) int2 g_csr[NE];    // (src, __float_as_int(norm)), node-ordered rows
__device__ float g_u1[NN], g_u2[NN], g_u3[NN];
__device__ __align__(16) float g_M1[DD * DC];
__device__ __align__(16) float g_M2[DD * DC];
__device__ __align__(16) float g_M3[DD * DC];
__device__ __align__(16) float g_Wc[DD * DC];
__device__ float g_cv[4 * DC];
__device__ __align__(16) float g_Y0[(size_t)NN * DC];
__device__ __align__(16) float g_Y1[(size_t)NN * DC];
__device__ float g_pool[NG * DC];
__device__ float g_usum[NG * 3];
__device__ float g_cnt[NG];

// ======== prep ========
__global__ void k_zero() {
    int i = blockIdx.x * blockDim.x + threadIdx.x;
    if (i < NN) { g_indeg[i] = 0; g_fill[i] = 0; }
    if (i < NG * DC) g_pool[i] = 0.0f;
    if (i < NG * 3) g_usum[i] = 0.0f;
    if (i < NG) g_cnt[i] = 0.0f;
}

__global__ void k_count(const int* __restrict__ ei) {
    int e = blockIdx.x * blockDim.x + threadIdx.x;
    if (e >= NE) return;
    atomicAdd(&g_indeg[ei[NE + e]], 1);
}

// per-block inclusive scan of indeg + block sums
__global__ void k_scan1() {
    __shared__ int s[SCAN_BS];
    int i = blockIdx.x * SCAN_BS + threadIdx.x;
    int v = (i < NN) ? g_indeg[i] : 0;
    s[threadIdx.x] = v;
    __syncthreads();
#pragma unroll
    for (int off = 1; off < SCAN_BS; off <<= 1) {
        int t = (threadIdx.x >= off) ? s[threadIdx.x - off] : 0;
        __syncthreads();
        s[threadIdx.x] += t;
        __syncthreads();
    }
    if (i < NN) g_scan_tmp[i] = s[threadIdx.x];
    if (threadIdx.x == SCAN_BS - 1) g_bsum[blockIdx.x] = s[threadIdx.x];
}

// fused base-computation + exclusive rowptr (replaces scan2 + scan3)
__global__ void k_scan3() {
    __shared__ int sred[SCAN_BS];
    int partial = 0;
    for (int j = threadIdx.x; j < blockIdx.x; j += SCAN_BS) partial += g_bsum[j];
    sred[threadIdx.x] = partial;
    __syncthreads();
#pragma unroll
    for (int off = SCAN_BS / 2; off > 0; off >>= 1) {
        if (threadIdx.x < off) sred[threadIdx.x] += sred[threadIdx.x + off];
        __syncthreads();
    }
    int base = sred[0];
    int i = blockIdx.x * SCAN_BS + threadIdx.x;
    if (i < NN) g_rowptr[i] = base + g_scan_tmp[i] - g_indeg[i];
}

__global__ void k_dinv(const int* __restrict__ batch) {
    int n = blockIdx.x * blockDim.x + threadIdx.x;
    if (n >= NN) return;
    g_dinv[n] = rsqrtf((float)g_indeg[n] + 1.0f);
    atomicAdd(&g_cnt[batch[n]], 1.0f);
}

__global__ void k_fill(const int* __restrict__ ei) {
    int e = blockIdx.x * blockDim.x + threadIdx.x;
    if (e >= NE) return;
    int s = ei[e];
    int d = ei[NE + e];
    int pos = g_rowptr[d] + atomicAdd(&g_fill[d], 1);
    g_csr[pos] = make_int2(s, __float_as_int(g_dinv[s] * g_dinv[d]));
}

// ======== weight chain: C[128,32] = A[128,128] @ B[128,32] ========
__global__ void k_mm(const float* __restrict__ A, const float* __restrict__ Bext,
                     int bsel, int csel) {
    const float* B = (bsel == 0) ? Bext : (bsel == 1) ? g_M3 : (bsel == 2) ? g_M2 : g_M1;
    float*       C = (csel == 0) ? g_M3 : (csel == 1) ? g_M2 : (csel == 2) ? g_M1 : g_Wc;
    int t = blockIdx.x * blockDim.x + threadIdx.x;
    int r = t >> 5, c = t & 31;
    float s = 0.0f;
#pragma unroll 8
    for (int k = 0; k < DD; k++) s += A[r * DD + k] * B[k * DC + c];
    C[r * DC + c] = s;
}

// c_i = b_i^T M_i  (M4 = fcW)
__global__ void k_cvec(const float* __restrict__ b1, const float* __restrict__ b2,
                       const float* __restrict__ b3, const float* __restrict__ b4,
                       const float* __restrict__ fcW) {
    int t = threadIdx.x;              // 128 threads
    int i = t >> 5, c = t & 31;
    const float* b = (i == 0) ? b1 : (i == 1) ? b2 : (i == 2) ? b3 : b4;
    const float* M = (i == 0) ? g_M1 : (i == 1) ? g_M2 : (i == 2) ? g_M3 : fcW;
    float s = 0.0f;
#pragma unroll 8
    for (int k = 0; k < DD; k++) s += b[k] * M[k * DC + c];
    g_cv[i * DC + c] = s;
}

// ======== Y0 = X @ Wc   (X:[NN,128], Wc:[128,32]) ========
__global__ __launch_bounds__(256) void k_gemmY(const float* __restrict__ X) {
    __shared__ float Ws[DD][DC];
    __shared__ float As[128][33];
    int t  = threadIdx.x;
    int m0 = blockIdx.x * 128;
    int rb = t >> 3;                  // 0..31
    int cg = (t & 7) << 2;            // col group of 4

#pragma unroll
    for (int i = 0; i < 4; i++) {
        int lin = t + i * 256;
        int r = lin >> 3, c4 = (lin & 7) << 2;
        *(float4*)&Ws[r][c4] = *(const float4*)(g_Wc + r * DC + c4);
    }

    float4 ac[4];
#pragma unroll
    for (int j = 0; j < 4; j++) ac[j] = make_float4(0.f, 0.f, 0.f, 0.f);

    for (int k0 = 0; k0 < DD; k0 += 32) {
        __syncthreads();
#pragma unroll
        for (int i = 0; i < 4; i++) {
            int lin = t + i * 256;
            int r = lin >> 3, c4 = (lin & 7) << 2;
            int gr = m0 + r;
            float4 v = make_float4(0.f, 0.f, 0.f, 0.f);
            if (gr < NN) v = *(const float4*)(X + (size_t)gr * DD + k0 + c4);
            As[r][c4 + 0] = v.x; As[r][c4 + 1] = v.y;
            As[r][c4 + 2] = v.z; As[r][c4 + 3] = v.w;
        }
        __syncthreads();
#pragma unroll
        for (int k = 0; k < 32; k++) {
            float4 wv = *(const float4*)&Ws[k0 + k][cg];
#pragma unroll
            for (int j = 0; j < 4; j++) {
                float a = As[rb + 32 * j][k];
                ac[j].x += a * wv.x; ac[j].y += a * wv.y;
                ac[j].z += a * wv.z; ac[j].w += a * wv.w;
            }
        }
    }

#pragma unroll
    for (int j = 0; j < 4; j++) {
        int gr = m0 + rb + 32 * j;
        if (gr < NN) *(float4*)(g_Y0 + (size_t)gr * DC + cg) = ac[j];
    }
}

// ======== scalar aggregate: u' = Â u ========
// stage 0: ones -> u1 ; stage 1: u1 -> u2 ; stage 2: u2 -> u3
__global__ void k_uagg(int stage) {
    int n = blockIdx.x * blockDim.x + threadIdx.x;
    if (n >= NN) return;
    const float* uin = (stage == 1) ? g_u1 : (stage == 2) ? g_u2 : nullptr;
    float*      uout = (stage == 0) ? g_u1 : (stage == 1) ? g_u2 : g_u3;
    float dv = g_dinv[n];
    float acc = (stage == 0) ? dv * dv : dv * dv * uin[n];
    int beg = g_rowptr[n], end = beg + g_indeg[n];
    if (stage == 0) {
        for (int e = beg; e < end; e++) acc += __int_as_float(g_csr[e].y);
    } else {
        for (int e = beg; e < end; e++) {
            int2 cv = g_csr[e];
            acc += __int_as_float(cv.y) * uin[cv.x];
        }
    }
    uout[n] = acc;
}

// ======== vector aggregate (D=32): Yout = Â Yin ========
// flip 0: Y0 -> Y1 ; flip 1: Y1 -> Y0
__global__ __launch_bounds__(256) void k_vagg(int flip) {
    const float* __restrict__ Yin  = flip ? g_Y1 : g_Y0;
    float*       __restrict__ Yout = flip ? g_Y0 : g_Y1;
    int gid = blockIdx.x * blockDim.x + threadIdx.x;
    int n   = gid >> 5;
    if (n >= NN) return;
    int l = gid & 31;
    float dv  = g_dinv[n];
    float acc = dv * dv * Yin[(size_t)n * DC + l];
    int beg = g_rowptr[n], end = beg + g_indeg[n];
    int e = beg;
    // unroll-8: deep MLP to cover L2 gather latency
    for (; e + 8 <= end; e += 8) {
        int2 c0 = g_csr[e],     c1 = g_csr[e + 1];
        int2 c2 = g_csr[e + 2], c3 = g_csr[e + 3];
        int2 c4 = g_csr[e + 4], c5 = g_csr[e + 5];
        int2 c6 = g_csr[e + 6], c7 = g_csr[e + 7];
        float v0 = Yin[(size_t)c0.x * DC + l], v1 = Yin[(size_t)c1.x * DC + l];
        float v2 = Yin[(size_t)c2.x * DC + l], v3 = Yin[(size_t)c3.x * DC + l];
        float v4 = Yin[(size_t)c4.x * DC + l], v5 = Yin[(size_t)c5.x * DC + l];
        float v6 = Yin[(size_t)c6.x * DC + l], v7 = Yin[(size_t)c7.x * DC + l];
        acc += __int_as_float(c0.y) * v0 + __int_as_float(c1.y) * v1
             + __int_as_float(c2.y) * v2 + __int_as_float(c3.y) * v3
             + __int_as_float(c4.y) * v4 + __int_as_float(c5.y) * v5
             + __int_as_float(c6.y) * v6 + __int_as_float(c7.y) * v7;
    }
    for (; e + 2 <= end; e += 2) {
        int2 c0 = g_csr[e], c1 = g_csr[e + 1];
        acc += __int_as_float(c0.y) * Yin[(size_t)c0.x * DC + l]
             + __int_as_float(c1.y) * Yin[(size_t)c1.x * DC + l];
    }
    if (e < end) {
        int2 cv = g_csr[e];
        acc += __int_as_float(cv.y) * Yin[(size_t)cv.x * DC + l];
    }
    Yout[(size_t)n * DC + l] = acc;
}

// ======== pooled sums (batch sorted -> chunked accumulate, rare flushes) ========
#define POOL_CHUNK 16
__global__ __launch_bounds__(256) void k_pool(const int* __restrict__ batch) {
    int gid = blockIdx.x * blockDim.x + threadIdx.x;
    int w   = gid >> 5;
    int n0  = w * POOL_CHUNK;
    if (n0 >= NN) return;
    int l = gid & 31;
    int cur = batch[n0];
    float acc = 0.0f;
    for (int i = 0; i < POOL_CHUNK && n0 + i < NN; i++) {
        int n = n0 + i;
        int g = batch[n];
        if (g != cur) {
            atomicAdd(&g_pool[cur * DC + l], acc);
            acc = 0.0f; cur = g;
        }
        acc += g_Y0[(size_t)n * DC + l];   // final Z lives in g_Y0
    }
    atomicAdd(&g_pool[cur * DC + l], acc);
}

__global__ void k_upool(const int* __restrict__ batch) {
    int t  = blockIdx.x * blockDim.x + threadIdx.x;
    int n0 = t * POOL_CHUNK;
    if (n0 >= NN) return;
    int cur = batch[n0];
    float s1 = 0.f, s2 = 0.f, s3 = 0.f;
    for (int i = 0; i < POOL_CHUNK && n0 + i < NN; i++) {
        int n = n0 + i;
        int g = batch[n];
        if (g != cur) {
            atomicAdd(&g_usum[cur * 3 + 0], s1);
            atomicAdd(&g_usum[cur * 3 + 1], s2);
            atomicAdd(&g_usum[cur * 3 + 2], s3);
            s1 = s2 = s3 = 0.f; cur = g;
        }
        s1 += g_u1[n]; s2 += g_u2[n]; s3 += g_u3[n];
    }
    atomicAdd(&g_usum[cur * 3 + 0], s1);
    atomicAdd(&g_usum[cur * 3 + 1], s2);
    atomicAdd(&g_usum[cur * 3 + 2], s3);
}

// ======== final: mean pool + rank-1 bias terms ========
__global__ void k_final(const float* __restrict__ fcb, float* __restrict__ out) {
    int g = blockIdx.x;
    int c = threadIdx.x;   // 32
    float cnt = g_cnt[g];
    float v = g_pool[g * DC + c]
            + g_usum[g * 3 + 2] * g_cv[0 * DC + c]      // u3 * (b1ᵀ W2W3W4 fcW)
            + g_usum[g * 3 + 1] * g_cv[1 * DC + c]      // u2 * (b2ᵀ W3W4 fcW)
            + g_usum[g * 3 + 0] * g_cv[2 * DC + c]      // u1 * (b3ᵀ W4 fcW)
            + cnt * (g_cv[3 * DC + c] + fcb[c]);        // 1  * (b4ᵀ fcW + fcb)
    out[g * DC + c] = v / fmaxf(cnt, 1.0f);
}

extern "C" void kernel_launch(void* const* d_in, const int* in_sizes, int n_in,
                              void* d_out, int out_size) {
    const float* x     = (const float*)d_in[0];
    const int*   ei    = (const int*)d_in[1];
    const int*   batch = (const int*)d_in[2];
    const float* W1 = (const float*)d_in[3];
    const float* b1 = (const float*)d_in[4];
    const float* W2 = (const float*)d_in[5];
    const float* b2 = (const float*)d_in[6];
    const float* W3 = (const float*)d_in[7];
    const float* b3 = (const float*)d_in[8];
    const float* W4 = (const float*)d_in[9];
    const float* b4 = (const float*)d_in[10];
    const float* fcW = (const float*)d_in[11];
    const float* fcb = (const float*)d_in[12];
    float* out = (float*)d_out;

    const int TB = 256;
    // CSR prep (node-ordered rows via scan)
    k_zero <<<(NN + TB - 1) / TB, TB>>>();
    k_count<<<(NE + TB - 1) / TB, TB>>>(ei);
    k_scan1<<<SCAN_NB, SCAN_BS>>>();
    k_scan3<<<SCAN_NB, SCAN_BS>>>();
    k_dinv <<<(NN + TB - 1) / TB, TB>>>(batch);
    k_fill <<<(NE + TB - 1) / TB, TB>>>(ei);

    // weight chain: M3 = W4 fcW; M2 = W3 M3; M1 = W2 M2; Wc = W1 M1
    k_mm<<<16, TB>>>(W4, fcW, 0, 0);
    k_mm<<<16, TB>>>(W3, nullptr, 1, 1);
    k_mm<<<16, TB>>>(W2, nullptr, 2, 2);
    k_mm<<<16, TB>>>(W1, nullptr, 3, 3);
    k_cvec<<<1, 128>>>(b1, b2, b3, b4, fcW);

    // Y0 = X @ Wc
    k_gemmY<<<(NN + 127) / 128, TB>>>(x);

    // u_k = Â^k 1
    k_uagg<<<(NN + TB - 1) / TB, TB>>>(0);
    k_uagg<<<(NN + TB - 1) / TB, TB>>>(1);
    k_uagg<<<(NN + TB - 1) / TB, TB>>>(2);

    // Z = Â^4 Y0   (ping-pong, ends in g_Y0)
    const int AGG_BLOCKS = (NN * 32 + TB - 1) / TB;   // 6250
    k_vagg<<<AGG_BLOCKS, TB>>>(0);
    k_vagg<<<AGG_BLOCKS, TB>>>(1);
    k_vagg<<<AGG_BLOCKS, TB>>>(0);
    k_vagg<<<AGG_BLOCKS, TB>>>(1);

    // pooling + final
    const int NCHUNK = (NN + POOL_CHUNK - 1) / POOL_CHUNK;  // 3125
    k_pool <<<(NCHUNK * 32 + TB - 1) / TB, TB>>>(batch);
    k_upool<<<(NCHUNK + TB - 1) / TB, TB>>>(batch);
    k_final<<<NG, DC>>>(fcb, out);
}

// round 11
// speedup vs baseline: 1.2839x; 1.0101x over previous
#include <cuda_runtime.h>
#include <cstddef>

#define NN 50000
#define NE 600000
#define DD 128
#define DC 32          // collapsed output width
#define NG 64

#define SCAN_BS 256
#define SCAN_NB ((NN + SCAN_BS - 1) / SCAN_BS)   // 196

#define VB 6250        // vector blocks per vagg (50000*32/256)
#define UB SCAN_NB     // scalar-u blocks appended (196)

// -------- scratch (device globals; never passed as kernel args from host) --------
__device__ int   g_indeg[NN];
__device__ float g_dinv[NN];
__device__ int   g_rowptr[NN];
__device__ int   g_fill[NN];
__device__ int   g_scan_tmp[NN];
__device__ int   g_bsum[SCAN_NB];
__device__ __align__(8) int2 g_csr[NE];    // (src, __float_as_int(norm)), node-ordered rows
__device__ float g_u1[NN], g_u2[NN], g_u3[NN];
__device__ __align__(16) float g_M1[DD * DC];
__device__ __align__(16) float g_M2[DD * DC];
__device__ __align__(16) float g_M3[DD * DC];
__device__ __align__(16) float g_Wc[DD * DC];
__device__ float g_cv[4 * DC];
__device__ __align__(16) float g_Y0[(size_t)NN * DC];
__device__ __align__(16) float g_Y1[(size_t)NN * DC];
__device__ float g_pool[NG * DC];
__device__ float g_usum[NG * 3];
__device__ float g_cnt[NG];

// ======== prep ========
__global__ void k_zero() {
    int i = blockIdx.x * blockDim.x + threadIdx.x;
    if (i < NN) { g_indeg[i] = 0; g_fill[i] = 0; }
    if (i < NG * DC) g_pool[i] = 0.0f;
    if (i < NG * 3) g_usum[i] = 0.0f;
    if (i < NG) g_cnt[i] = 0.0f;
}

__global__ void k_count(const int* __restrict__ ei) {
    int e = blockIdx.x * blockDim.x + threadIdx.x;
    if (e >= NE) return;
    atomicAdd(&g_indeg[ei[NE + e]], 1);
}

// per-block inclusive scan of indeg + block sums
__global__ void k_scan1() {
    __shared__ int s[SCAN_BS];
    int i = blockIdx.x * SCAN_BS + threadIdx.x;
    int v = (i < NN) ? g_indeg[i] : 0;
    s[threadIdx.x] = v;
    __syncthreads();
#pragma unroll
    for (int off = 1; off < SCAN_BS; off <<= 1) {
        int t = (threadIdx.x >= off) ? s[threadIdx.x - off] : 0;
        __syncthreads();
        s[threadIdx.x] += t;
        __syncthreads();
    }
    if (i < NN) g_scan_tmp[i] = s[threadIdx.x];
    if (threadIdx.x == SCAN_BS - 1) g_bsum[blockIdx.x] = s[threadIdx.x];
}

// fused: block-base reduction + exclusive rowptr + dinv + per-graph counts
__global__ void k_scan3(const int* __restrict__ batch) {
    __shared__ int sred[SCAN_BS];
    int partial = 0;
    for (int j = threadIdx.x; j < blockIdx.x; j += SCAN_BS) partial += g_bsum[j];
    sred[threadIdx.x] = partial;
    __syncthreads();
#pragma unroll
    for (int off = SCAN_BS / 2; off > 0; off >>= 1) {
        if (threadIdx.x < off) sred[threadIdx.x] += sred[threadIdx.x + off];
        __syncthreads();
    }
    int base = sred[0];
    int i = blockIdx.x * SCAN_BS + threadIdx.x;
    if (i < NN) {
        int d = g_indeg[i];
        g_rowptr[i] = base + g_scan_tmp[i] - d;
        g_dinv[i]   = rsqrtf((float)d + 1.0f);
        atomicAdd(&g_cnt[batch[i]], 1.0f);
    }
}

__global__ void k_fill(const int* __restrict__ ei) {
    int e = blockIdx.x * blockDim.x + threadIdx.x;
    if (e >= NE) return;
    int s = ei[e];
    int d = ei[NE + e];
    int pos = g_rowptr[d] + atomicAdd(&g_fill[d], 1);
    g_csr[pos] = make_int2(s, __float_as_int(g_dinv[s] * g_dinv[d]));
}

// ======== weight chain: C[128,32] = A[128,128] @ B[128,32] ========
__global__ void k_mm(const float* __restrict__ A, const float* __restrict__ Bext,
                     int bsel, int csel) {
    const float* B = (bsel == 0) ? Bext : (bsel == 1) ? g_M3 : (bsel == 2) ? g_M2 : g_M1;
    float*       C = (csel == 0) ? g_M3 : (csel == 1) ? g_M2 : (csel == 2) ? g_M1 : g_Wc;
    int t = blockIdx.x * blockDim.x + threadIdx.x;
    int r = t >> 5, c = t & 31;
    float s = 0.0f;
#pragma unroll 8
    for (int k = 0; k < DD; k++) s += A[r * DD + k] * B[k * DC + c];
    C[r * DC + c] = s;
}

// c_i = b_i^T M_i  (M4 = fcW)
__global__ void k_cvec(const float* __restrict__ b1, const float* __restrict__ b2,
                       const float* __restrict__ b3, const float* __restrict__ b4,
                       const float* __restrict__ fcW) {
    int t = threadIdx.x;              // 128 threads
    int i = t >> 5, c = t & 31;
    const float* b = (i == 0) ? b1 : (i == 1) ? b2 : (i == 2) ? b3 : b4;
    const float* M = (i == 0) ? g_M1 : (i == 1) ? g_M2 : (i == 2) ? g_M3 : fcW;
    float s = 0.0f;
#pragma unroll 8
    for (int k = 0; k < DD; k++) s += b[k] * M[k * DC + c];
    g_cv[i * DC + c] = s;
}

// ======== Y0 = X @ Wc   (X:[NN,128], Wc:[128,32]) ========
__global__ __launch_bounds__(256) void k_gemmY(const float* __restrict__ X) {
    __shared__ float Ws[DD][DC];
    __shared__ float As[128][33];
    int t  = threadIdx.x;
    int m0 = blockIdx.x * 128;
    int rb = t >> 3;                  // 0..31
    int cg = (t & 7) << 2;            // col group of 4

#pragma unroll
    for (int i = 0; i < 4; i++) {
        int lin = t + i * 256;
        int r = lin >> 3, c4 = (lin & 7) << 2;
        *(float4*)&Ws[r][c4] = *(const float4*)(g_Wc + r * DC + c4);
    }

    float4 ac[4];
#pragma unroll
    for (int j = 0; j < 4; j++) ac[j] = make_float4(0.f, 0.f, 0.f, 0.f);

    for (int k0 = 0; k0 < DD; k0 += 32) {
        __syncthreads();
#pragma unroll
        for (int i = 0; i < 4; i++) {
            int lin = t + i * 256;
            int r = lin >> 3, c4 = (lin & 7) << 2;
            int gr = m0 + r;
            float4 v = make_float4(0.f, 0.f, 0.f, 0.f);
            if (gr < NN) v = *(const float4*)(X + (size_t)gr * DD + k0 + c4);
            As[r][c4 + 0] = v.x; As[r][c4 + 1] = v.y;
            As[r][c4 + 2] = v.z; As[r][c4 + 3] = v.w;
        }
        __syncthreads();
#pragma unroll
        for (int k = 0; k < 32; k++) {
            float4 wv = *(const float4*)&Ws[k0 + k][cg];
#pragma unroll
            for (int j = 0; j < 4; j++) {
                float a = As[rb + 32 * j][k];
                ac[j].x += a * wv.x; ac[j].y += a * wv.y;
                ac[j].z += a * wv.z; ac[j].w += a * wv.w;
            }
        }
    }

#pragma unroll
    for (int j = 0; j < 4; j++) {
        int gr = m0 + rb + 32 * j;
        if (gr < NN) *(float4*)(g_Y0 + (size_t)gr * DC + cg) = ac[j];
    }
}

// ======== fused vector aggregate + block-specialized scalar u-chain ========
// Blocks [0, VB):      Yout = Â Yin   (clean R10 loop, untouched)
// Blocks [VB, VB+UB):  u-chain stage (STAGE 1: 1->u1, 2: u1->u2, 3: u2->u3)
// STAGE 1,3: Y0->Y1 ;  STAGE 2,4: Y1->Y0.  Final result lands in g_Y0.
template <int STAGE>
__global__ __launch_bounds__(256) void k_vagg() {
    const float* __restrict__ Yin  = (STAGE == 1 || STAGE == 3) ? g_Y0 : g_Y1;
    float*       __restrict__ Yout = (STAGE == 1 || STAGE == 3) ? g_Y1 : g_Y0;

    if (blockIdx.x < VB) {
        int gid = blockIdx.x * blockDim.x + threadIdx.x;
        int n   = gid >> 5;
        if (n >= NN) return;
        int l = gid & 31;
        float dv  = g_dinv[n];
        float acc = dv * dv * Yin[(size_t)n * DC + l];
        int beg = g_rowptr[n], end = beg + g_indeg[n];
        int e = beg;
        for (; e + 8 <= end; e += 8) {
            int2 c0 = g_csr[e],     c1 = g_csr[e + 1];
            int2 c2 = g_csr[e + 2], c3 = g_csr[e + 3];
            int2 c4 = g_csr[e + 4], c5 = g_csr[e + 5];
            int2 c6 = g_csr[e + 6], c7 = g_csr[e + 7];
            float v0 = Yin[(size_t)c0.x * DC + l], v1 = Yin[(size_t)c1.x * DC + l];
            float v2 = Yin[(size_t)c2.x * DC + l], v3 = Yin[(size_t)c3.x * DC + l];
            float v4 = Yin[(size_t)c4.x * DC + l], v5 = Yin[(size_t)c5.x * DC + l];
            float v6 = Yin[(size_t)c6.x * DC + l], v7 = Yin[(size_t)c7.x * DC + l];
            acc += __int_as_float(c0.y) * v0 + __int_as_float(c1.y) * v1
                 + __int_as_float(c2.y) * v2 + __int_as_float(c3.y) * v3
                 + __int_as_float(c4.y) * v4 + __int_as_float(c5.y) * v5
                 + __int_as_float(c6.y) * v6 + __int_as_float(c7.y) * v7;
        }
        for (; e + 2 <= end; e += 2) {
            int2 c0 = g_csr[e], c1 = g_csr[e + 1];
            acc += __int_as_float(c0.y) * Yin[(size_t)c0.x * DC + l]
                 + __int_as_float(c1.y) * Yin[(size_t)c1.x * DC + l];
        }
        if (e < end) {
            int2 cv = g_csr[e];
            acc += __int_as_float(cv.y) * Yin[(size_t)cv.x * DC + l];
        }
        Yout[(size_t)n * DC + l] = acc;
    } else if (STAGE < 4) {
        // scalar u-chain stage (block-uniform path; clean loop)
        int n = (blockIdx.x - VB) * blockDim.x + threadIdx.x;
        if (n >= NN) return;
        const float* uin = (STAGE == 2) ? g_u1 : (STAGE == 3) ? g_u2 : nullptr;
        float*      uout = (STAGE == 1) ? g_u1 : (STAGE == 2) ? g_u2 : g_u3;
        float dv = g_dinv[n];
        float acc = (STAGE == 1) ? dv * dv : dv * dv * uin[n];
        int beg = g_rowptr[n], end = beg + g_indeg[n];
        if (STAGE == 1) {
            for (int e = beg; e < end; e++) acc += __int_as_float(g_csr[e].y);
        } else {
            for (int e = beg; e < end; e++) {
                int2 cv = g_csr[e];
                acc += __int_as_float(cv.y) * uin[cv.x];
            }
        }
        uout[n] = acc;
    }
}

// ======== pooled sums (batch sorted -> chunked accumulate, rare flushes) ========
#define POOL_CHUNK 16
__global__ __launch_bounds__(256) void k_pool(const int* __restrict__ batch) {
    int gid = blockIdx.x * blockDim.x + threadIdx.x;
    int w   = gid >> 5;
    int n0  = w * POOL_CHUNK;
    if (n0 >= NN) return;
    int l = gid & 31;
    int cur = batch[n0];
    float acc = 0.0f;
    for (int i = 0; i < POOL_CHUNK && n0 + i < NN; i++) {
        int n = n0 + i;
        int g = batch[n];
        if (g != cur) {
            atomicAdd(&g_pool[cur * DC + l], acc);
            acc = 0.0f; cur = g;
        }
        acc += g_Y0[(size_t)n * DC + l];   // final Z lives in g_Y0
    }
    atomicAdd(&g_pool[cur * DC + l], acc);
}

__global__ void k_upool(const int* __restrict__ batch) {
    int t  = blockIdx.x * blockDim.x + threadIdx.x;
    int n0 = t * POOL_CHUNK;
    if (n0 >= NN) return;
    int cur = batch[n0];
    float s1 = 0.f, s2 = 0.f, s3 = 0.f;
    for (int i = 0; i < POOL_CHUNK && n0 + i < NN; i++) {
        int n = n0 + i;
        int g = batch[n];
        if (g != cur) {
            atomicAdd(&g_usum[cur * 3 + 0], s1);
            atomicAdd(&g_usum[cur * 3 + 1], s2);
            atomicAdd(&g_usum[cur * 3 + 2], s3);
            s1 = s2 = s3 = 0.f; cur = g;
        }
        s1 += g_u1[n]; s2 += g_u2[n]; s3 += g_u3[n];
    }
    atomicAdd(&g_usum[cur * 3 + 0], s1);
    atomicAdd(&g_usum[cur * 3 + 1], s2);
    atomicAdd(&g_usum[cur * 3 + 2], s3);
}

// ======== final: mean pool + rank-1 bias terms ========
__global__ void k_final(const float* __restrict__ fcb, float* __restrict__ out) {
    int g = blockIdx.x;
    int c = threadIdx.x;   // 32
    float cnt = g_cnt[g];
    float v = g_pool[g * DC + c]
            + g_usum[g * 3 + 2] * g_cv[0 * DC + c]      // u3 * (b1ᵀ W2W3W4 fcW)
            + g_usum[g * 3 + 1] * g_cv[1 * DC + c]      // u2 * (b2ᵀ W3W4 fcW)
            + g_usum[g * 3 + 0] * g_cv[2 * DC + c]      // u1 * (b3ᵀ W4 fcW)
            + cnt * (g_cv[3 * DC + c] + fcb[c]);        // 1  * (b4ᵀ fcW + fcb)
    out[g * DC + c] = v / fmaxf(cnt, 1.0f);
}

extern "C" void kernel_launch(void* const* d_in, const int* in_sizes, int n_in,
                              void* d_out, int out_size) {
    const float* x     = (const float*)d_in[0];
    const int*   ei    = (const int*)d_in[1];
    const int*   batch = (const int*)d_in[2];
    const float* W1 = (const float*)d_in[3];
    const float* b1 = (const float*)d_in[4];
    const float* W2 = (const float*)d_in[5];
    const float* b2 = (const float*)d_in[6];
    const float* W3 = (const float*)d_in[7];
    const float* b3 = (const float*)d_in[8];
    const float* W4 = (const float*)d_in[9];
    const float* b4 = (const float*)d_in[10];
    const float* fcW = (const float*)d_in[11];
    const float* fcb = (const float*)d_in[12];
    float* out = (float*)d_out;

    const int TB = 256;
    // CSR prep (node-ordered rows via scan; dinv+cnt fused into scan3)
    k_zero <<<(NN + TB - 1) / TB, TB>>>();
    k_count<<<(NE + TB - 1) / TB, TB>>>(ei);
    k_scan1<<<SCAN_NB, SCAN_BS>>>();
    k_scan3<<<SCAN_NB, SCAN_BS>>>(batch);
    k_fill <<<(NE + TB - 1) / TB, TB>>>(ei);

    // weight chain: M3 = W4 fcW; M2 = W3 M3; M1 = W2 M2; Wc = W1 M1
    k_mm<<<16, TB>>>(W4, fcW, 0, 0);
    k_mm<<<16, TB>>>(W3, nullptr, 1, 1);
    k_mm<<<16, TB>>>(W2, nullptr, 2, 2);
    k_mm<<<16, TB>>>(W1, nullptr, 3, 3);
    k_cvec<<<1, 128>>>(b1, b2, b3, b4, fcW);

    // Y0 = X @ Wc
    k_gemmY<<<(NN + 127) / 128, TB>>>(x);

    // Â-powers with block-specialized u-chain riding along
    k_vagg<1><<<VB + UB, TB>>>();
    k_vagg<2><<<VB + UB, TB>>>();
    k_vagg<3><<<VB + UB, TB>>>();
    k_vagg<4><<<VB, TB>>>();

    // pooling + final
    const int NCHUNK = (NN + POOL_CHUNK - 1) / POOL_CHUNK;  // 3125
    k_pool <<<(NCHUNK * 32 + TB - 1) / TB, TB>>>(batch);
    k_upool<<<(NCHUNK + TB - 1) / TB, TB>>>(batch);
    k_final<<<NG, DC>>>(fcb, out);
}

// round 12
// speedup vs baseline: 1.5202x; 1.1841x over previous
#include <cuda_runtime.h>
#include <cstddef>

#define NN 50000
#define NE 600000
#define DD 128
#define DC 32          // collapsed output width
#define NG 64

#define SCAN_BS 256
#define SCAN_NB ((NN + SCAN_BS - 1) / SCAN_BS)   // 196

#define VB 6250        // vector blocks per vagg (50000*32/256)
#define UB SCAN_NB     // scalar-u blocks appended (196)

// -------- scratch (device globals; never passed as kernel args from host) --------
__device__ int   g_indeg[NN];
__device__ float g_dinv[NN];
__device__ int   g_rowptr[NN];
__device__ int   g_fill[NN];
__device__ int   g_scan_tmp[NN];
__device__ int   g_bsum[SCAN_NB];
__device__ __align__(8) int2 g_csr[NE];    // (src, __float_as_int(norm)), node-ordered rows
__device__ float g_u1[NN], g_u2[NN], g_u3[NN];
__device__ __align__(16) float g_M1[DD * DC];
__device__ __align__(16) float g_M2[DD * DC];
__device__ __align__(16) float g_M3[DD * DC];
__device__ __align__(16) float g_Wc[DD * DC];
__device__ float g_cv[4 * DC];
__device__ __align__(16) float g_Y0[(size_t)NN * DC];
__device__ __align__(16) float g_Y1[(size_t)NN * DC];
__device__ float g_pool[NG * DC];
__device__ float g_usum[NG * 3];

// ======== prep ========
__global__ void k_zero() {
    int i = blockIdx.x * blockDim.x + threadIdx.x;
    if (i < NN) { g_indeg[i] = 0; g_fill[i] = 0; }
    if (i < NG * DC) g_pool[i] = 0.0f;
    if (i < NG * 3) g_usum[i] = 0.0f;
}

__global__ void k_count(const int* __restrict__ ei) {
    int e = blockIdx.x * blockDim.x + threadIdx.x;
    if (e >= NE) return;
    atomicAdd(&g_indeg[ei[NE + e]], 1);
}

// per-block inclusive scan of indeg + block sums
__global__ void k_scan1() {
    __shared__ int s[SCAN_BS];
    int i = blockIdx.x * SCAN_BS + threadIdx.x;
    int v = (i < NN) ? g_indeg[i] : 0;
    s[threadIdx.x] = v;
    __syncthreads();
#pragma unroll
    for (int off = 1; off < SCAN_BS; off <<= 1) {
        int t = (threadIdx.x >= off) ? s[threadIdx.x - off] : 0;
        __syncthreads();
        s[threadIdx.x] += t;
        __syncthreads();
    }
    if (i < NN) g_scan_tmp[i] = s[threadIdx.x];
    if (threadIdx.x == SCAN_BS - 1) g_bsum[blockIdx.x] = s[threadIdx.x];
}

// fused: block-base reduction + exclusive rowptr + dinv  (NO g_cnt atomics —
// the 50000-onto-64-address sorted atomic was a ~32us L2 serialization)
__global__ void k_scan3() {
    __shared__ int sred[SCAN_BS];
    int partial = 0;
    for (int j = threadIdx.x; j < blockIdx.x; j += SCAN_BS) partial += g_bsum[j];
    sred[threadIdx.x] = partial;
    __syncthreads();
#pragma unroll
    for (int off = SCAN_BS / 2; off > 0; off >>= 1) {
        if (threadIdx.x < off) sred[threadIdx.x] += sred[threadIdx.x + off];
        __syncthreads();
    }
    int base = sred[0];
    int i = blockIdx.x * SCAN_BS + threadIdx.x;
    if (i < NN) {
        int d = g_indeg[i];
        g_rowptr[i] = base + g_scan_tmp[i] - d;
        g_dinv[i]   = rsqrtf((float)d + 1.0f);
    }
}

__global__ void k_fill(const int* __restrict__ ei) {
    int e = blockIdx.x * blockDim.x + threadIdx.x;
    if (e >= NE) return;
    int s = ei[e];
    int d = ei[NE + e];
    int pos = g_rowptr[d] + atomicAdd(&g_fill[d], 1);
    g_csr[pos] = make_int2(s, __float_as_int(g_dinv[s] * g_dinv[d]));
}

// ======== weight chain: C[128,32] = A[128,128] @ B[128,32] ========
__global__ void k_mm(const float* __restrict__ A, const float* __restrict__ Bext,
                     int bsel, int csel) {
    const float* B = (bsel == 0) ? Bext : (bsel == 1) ? g_M3 : (bsel == 2) ? g_M2 : g_M1;
    float*       C = (csel == 0) ? g_M3 : (csel == 1) ? g_M2 : (csel == 2) ? g_M1 : g_Wc;
    int t = blockIdx.x * blockDim.x + threadIdx.x;
    int r = t >> 5, c = t & 31;
    float s = 0.0f;
#pragma unroll 8
    for (int k = 0; k < DD; k++) s += A[r * DD + k] * B[k * DC + c];
    C[r * DC + c] = s;
}

// c_i = b_i^T M_i  (M4 = fcW)
__global__ void k_cvec(const float* __restrict__ b1, const float* __restrict__ b2,
                       const float* __restrict__ b3, const float* __restrict__ b4,
                       const float* __restrict__ fcW) {
    int t = threadIdx.x;              // 128 threads
    int i = t >> 5, c = t & 31;
    const float* b = (i == 0) ? b1 : (i == 1) ? b2 : (i == 2) ? b3 : b4;
    const float* M = (i == 0) ? g_M1 : (i == 1) ? g_M2 : (i == 2) ? g_M3 : fcW;
    float s = 0.0f;
#pragma unroll 8
    for (int k = 0; k < DD; k++) s += b[k] * M[k * DC + c];
    g_cv[i * DC + c] = s;
}

// ======== Y0 = X @ Wc   (X:[NN,128], Wc:[128,32]) ========
__global__ __launch_bounds__(256) void k_gemmY(const float* __restrict__ X) {
    __shared__ float Ws[DD][DC];
    __shared__ float As[128][33];
    int t  = threadIdx.x;
    int m0 = blockIdx.x * 128;
    int rb = t >> 3;                  // 0..31
    int cg = (t & 7) << 2;            // col group of 4

#pragma unroll
    for (int i = 0; i < 4; i++) {
        int lin = t + i * 256;
        int r = lin >> 3, c4 = (lin & 7) << 2;
        *(float4*)&Ws[r][c4] = *(const float4*)(g_Wc + r * DC + c4);
    }

    float4 ac[4];
#pragma unroll
    for (int j = 0; j < 4; j++) ac[j] = make_float4(0.f, 0.f, 0.f, 0.f);

    for (int k0 = 0; k0 < DD; k0 += 32) {
        __syncthreads();
#pragma unroll
        for (int i = 0; i < 4; i++) {
            int lin = t + i * 256;
            int r = lin >> 3, c4 = (lin & 7) << 2;
            int gr = m0 + r;
            float4 v = make_float4(0.f, 0.f, 0.f, 0.f);
            if (gr < NN) v = *(const float4*)(X + (size_t)gr * DD + k0 + c4);
            As[r][c4 + 0] = v.x; As[r][c4 + 1] = v.y;
            As[r][c4 + 2] = v.z; As[r][c4 + 3] = v.w;
        }
        __syncthreads();
#pragma unroll
        for (int k = 0; k < 32; k++) {
            float4 wv = *(const float4*)&Ws[k0 + k][cg];
#pragma unroll
            for (int j = 0; j < 4; j++) {
                float a = As[rb + 32 * j][k];
                ac[j].x += a * wv.x; ac[j].y += a * wv.y;
                ac[j].z += a * wv.z; ac[j].w += a * wv.w;
            }
        }
    }

#pragma unroll
    for (int j = 0; j < 4; j++) {
        int gr = m0 + rb + 32 * j;
        if (gr < NN) *(float4*)(g_Y0 + (size_t)gr * DC + cg) = ac[j];
    }
}

// ======== fused vector aggregate + block-specialized scalar u-chain ========
// Blocks [0, VB):      Yout = Â Yin   (clean loop)
// Blocks [VB, VB+UB):  u-chain stage (STAGE 1: 1->u1, 2: u1->u2, 3: u2->u3)
// STAGE 1,3: Y0->Y1 ;  STAGE 2,4: Y1->Y0.  Final result lands in g_Y0.
template <int STAGE>
__global__ __launch_bounds__(256) void k_vagg() {
    const float* __restrict__ Yin  = (STAGE == 1 || STAGE == 3) ? g_Y0 : g_Y1;
    float*       __restrict__ Yout = (STAGE == 1 || STAGE == 3) ? g_Y1 : g_Y0;

    if (blockIdx.x < VB) {
        int gid = blockIdx.x * blockDim.x + threadIdx.x;
        int n   = gid >> 5;
        if (n >= NN) return;
        int l = gid & 31;
        float dv  = g_dinv[n];
        float acc = dv * dv * Yin[(size_t)n * DC + l];
        int beg = g_rowptr[n], end = beg + g_indeg[n];
        int e = beg;
        for (; e + 8 <= end; e += 8) {
            int2 c0 = g_csr[e],     c1 = g_csr[e + 1];
            int2 c2 = g_csr[e + 2], c3 = g_csr[e + 3];
            int2 c4 = g_csr[e + 4], c5 = g_csr[e + 5];
            int2 c6 = g_csr[e + 6], c7 = g_csr[e + 7];
            float v0 = Yin[(size_t)c0.x * DC + l], v1 = Yin[(size_t)c1.x * DC + l];
            float v2 = Yin[(size_t)c2.x * DC + l], v3 = Yin[(size_t)c3.x * DC + l];
            float v4 = Yin[(size_t)c4.x * DC + l], v5 = Yin[(size_t)c5.x * DC + l];
            float v6 = Yin[(size_t)c6.x * DC + l], v7 = Yin[(size_t)c7.x * DC + l];
            acc += __int_as_float(c0.y) * v0 + __int_as_float(c1.y) * v1
                 + __int_as_float(c2.y) * v2 + __int_as_float(c3.y) * v3
                 + __int_as_float(c4.y) * v4 + __int_as_float(c5.y) * v5
                 + __int_as_float(c6.y) * v6 + __int_as_float(c7.y) * v7;
        }
        for (; e + 2 <= end; e += 2) {
            int2 c0 = g_csr[e], c1 = g_csr[e + 1];
            acc += __int_as_float(c0.y) * Yin[(size_t)c0.x * DC + l]
                 + __int_as_float(c1.y) * Yin[(size_t)c1.x * DC + l];
        }
        if (e < end) {
            int2 cv = g_csr[e];
            acc += __int_as_float(cv.y) * Yin[(size_t)cv.x * DC + l];
        }
        Yout[(size_t)n * DC + l] = acc;
    } else if (STAGE < 4) {
        // scalar u-chain stage (block-uniform path; clean loop)
        int n = (blockIdx.x - VB) * blockDim.x + threadIdx.x;
        if (n >= NN) return;
        const float* uin = (STAGE == 2) ? g_u1 : (STAGE == 3) ? g_u2 : nullptr;
        float*      uout = (STAGE == 1) ? g_u1 : (STAGE == 2) ? g_u2 : g_u3;
        float dv = g_dinv[n];
        float acc = (STAGE == 1) ? dv * dv : dv * dv * uin[n];
        int beg = g_rowptr[n], end = beg + g_indeg[n];
        if (STAGE == 1) {
            for (int e = beg; e < end; e++) acc += __int_as_float(g_csr[e].y);
        } else {
            for (int e = beg; e < end; e++) {
                int2 cv = g_csr[e];
                acc += __int_as_float(cv.y) * uin[cv.x];
            }
        }
        uout[n] = acc;
    }
}

// ======== pooled sums (batch sorted -> chunked accumulate, rare flushes) ========
#define POOL_CHUNK 16
__global__ __launch_bounds__(256) void k_pool(const int* __restrict__ batch) {
    int gid = blockIdx.x * blockDim.x + threadIdx.x;
    int w   = gid >> 5;
    int n0  = w * POOL_CHUNK;
    if (n0 >= NN) return;
    int l = gid & 31;
    int cur = batch[n0];
    float acc = 0.0f;
    for (int i = 0; i < POOL_CHUNK && n0 + i < NN; i++) {
        int n = n0 + i;
        int g = batch[n];
        if (g != cur) {
            atomicAdd(&g_pool[cur * DC + l], acc);
            acc = 0.0f; cur = g;
        }
        acc += g_Y0[(size_t)n * DC + l];   // final Z lives in g_Y0
    }
    atomicAdd(&g_pool[cur * DC + l], acc);
}

__global__ void k_upool(const int* __restrict__ batch) {
    int t  = blockIdx.x * blockDim.x + threadIdx.x;
    int n0 = t * POOL_CHUNK;
    if (n0 >= NN) return;
    int cur = batch[n0];
    float s1 = 0.f, s2 = 0.f, s3 = 0.f;
    for (int i = 0; i < POOL_CHUNK && n0 + i < NN; i++) {
        int n = n0 + i;
        int g = batch[n];
        if (g != cur) {
            atomicAdd(&g_usum[cur * 3 + 0], s1);
            atomicAdd(&g_usum[cur * 3 + 1], s2);
            atomicAdd(&g_usum[cur * 3 + 2], s3);
            s1 = s2 = s3 = 0.f; cur = g;
        }
        s1 += g_u1[n]; s2 += g_u2[n]; s3 += g_u3[n];
    }
    atomicAdd(&g_usum[cur * 3 + 0], s1);
    atomicAdd(&g_usum[cur * 3 + 1], s2);
    atomicAdd(&g_usum[cur * 3 + 2], s3);
}

// ======== final: mean pool + rank-1 bias terms; cnt via binary search ========
__global__ void k_final(const int* __restrict__ batch,
                        const float* __restrict__ fcb, float* __restrict__ out) {
    int g = blockIdx.x;
    int c = threadIdx.x;   // 32
    // cnt[g] = lower_bound(batch, g+1) - lower_bound(batch, g)  (batch sorted)
    int lo = 0, hi = NN;
    while (lo < hi) { int m = (lo + hi) >> 1; if (batch[m] < g) lo = m + 1; else hi = m; }
    int lo2 = lo, hi2 = NN;
    while (lo2 < hi2) { int m = (lo2 + hi2) >> 1; if (batch[m] <= g) lo2 = m + 1; else hi2 = m; }
    float cnt = (float)(lo2 - lo);

    float v = g_pool[g * DC + c]
            + g_usum[g * 3 + 2] * g_cv[0 * DC + c]      // u3 * (b1ᵀ W2W3W4 fcW)
            + g_usum[g * 3 + 1] * g_cv[1 * DC + c]      // u2 * (b2ᵀ W3W4 fcW)
            + g_usum[g * 3 + 0] * g_cv[2 * DC + c]      // u1 * (b3ᵀ W4 fcW)
            + cnt * (g_cv[3 * DC + c] + fcb[c]);        // 1  * (b4ᵀ fcW + fcb)
    out[g * DC + c] = v / fmaxf(cnt, 1.0f);
}

extern "C" void kernel_launch(void* const* d_in, const int* in_sizes, int n_in,
                              void* d_out, int out_size) {
    const float* x     = (const float*)d_in[0];
    const int*   ei    = (const int*)d_in[1];
    const int*   batch = (const int*)d_in[2];
    const float* W1 = (const float*)d_in[3];
    const float* b1 = (const float*)d_in[4];
    const float* W2 = (const float*)d_in[5];
    const float* b2 = (const float*)d_in[6];
    const float* W3 = (const float*)d_in[7];
    const float* b3 = (const float*)d_in[8];
    const float* W4 = (const float*)d_in[9];
    const float* b4 = (const float*)d_in[10];
    const float* fcW = (const float*)d_in[11];
    const float* fcb = (const float*)d_in[12];
    float* out = (float*)d_out;

    const int TB = 256;
    // CSR prep (node-ordered rows via scan; dinv fused into scan3, no atomics)
    k_zero <<<(NN + TB - 1) / TB, TB>>>();
    k_count<<<(NE + TB - 1) / TB, TB>>>(ei);
    k_scan1<<<SCAN_NB, SCAN_BS>>>();
    k_scan3<<<SCAN_NB, SCAN_BS>>>();
    k_fill <<<(NE + TB - 1) / TB, TB>>>(ei);

    // weight chain: M3 = W4 fcW; M2 = W3 M3; M1 = W2 M2; Wc = W1 M1
    k_mm<<<16, TB>>>(W4, fcW, 0, 0);
    k_mm<<<16, TB>>>(W3, nullptr, 1, 1);
    k_mm<<<16, TB>>>(W2, nullptr, 2, 2);
    k_mm<<<16, TB>>>(W1, nullptr, 3, 3);
    k_cvec<<<1, 128>>>(b1, b2, b3, b4, fcW);

    // Y0 = X @ Wc
    k_gemmY<<<(NN + 127) / 128, TB>>>(x);

    // Â-powers with block-specialized u-chain riding along
    k_vagg<1><<<VB + UB, TB>>>();
    k_vagg<2><<<VB + UB, TB>>>();
    k_vagg<3><<<VB + UB, TB>>>();
    k_vagg<4><<<VB, TB>>>();

    // pooling + final
    const int NCHUNK = (NN + POOL_CHUNK - 1) / POOL_CHUNK;  // 3125
    k_pool <<<(NCHUNK * 32 + TB - 1) / TB, TB>>>(batch);
    k_upool<<<(NCHUNK + TB - 1) / TB, TB>>>(batch);
    k_final<<<NG, DC>>>(batch, fcb, out);
}

// round 13
// speedup vs baseline: 1.7360x; 1.1419x over previous
#include <cuda_runtime.h>
#include <cstddef>

#define NN 50000
#define NE 600000
#define DD 128
#define DC 32          // collapsed output width
#define NG 64

#define SCAN_BS 256
#define SCAN_NB ((NN + SCAN_BS - 1) / SCAN_BS)   // 196

#define VB 6250        // vector blocks per vagg (50000*32/256)
#define UB SCAN_NB     // scalar-u blocks appended (196)

#define ZB  SCAN_NB                     // zero blocks (196, covers NN and NG*DC)
#define CB  ((NE + 255) / 256)          // count/fill blocks (2344)
#define MMB 16                          // blocks per 128x32 weight mm
#define GYB ((NN + 127) / 128)          // gemmY blocks (391)
#define PB  ((VB / 16) + 1)             // pool blocks (391: 3125 warps)
#define UPB ((NN / 16 + 255) / 256)     // upool blocks (13)

// -------- scratch (device globals; never passed as kernel args from host) --------
__device__ int   g_indeg[NN];
__device__ float g_dinv[NN];
__device__ int   g_rowptr[NN];
__device__ int   g_rank[NE];           // per-edge slot within dst segment
__device__ int   g_scan_tmp[NN];
__device__ int   g_bsum[SCAN_NB];
__device__ __align__(8) int2 g_csr[NE];    // (src, __float_as_int(norm)), node-ordered rows
__device__ float g_u1[NN], g_u2[NN], g_u3[NN];
__device__ __align__(16) float g_M1[DD * DC];
__device__ __align__(16) float g_M2[DD * DC];
__device__ __align__(16) float g_M3[DD * DC];
__device__ __align__(16) float g_Wc[DD * DC];
__device__ float g_cv[4 * DC];
__device__ __align__(16) float g_Y0[(size_t)NN * DC];
__device__ __align__(16) float g_Y1[(size_t)NN * DC];
__device__ float g_pool[NG * DC];
__device__ float g_usum[NG * 3];

// ======== shared mm tile: C[128,32] = A[128,128] @ B[128,32], 16 blocks ========
__device__ __forceinline__ void mm_tile(const float* __restrict__ A,
                                        const float* __restrict__ B,
                                        float* __restrict__ C, int blk) {
    int t = blk * 256 + threadIdx.x;
    int r = t >> 5, c = t & 31;
    float s = 0.0f;
#pragma unroll 8
    for (int k = 0; k < DD; k++) s += A[r * DD + k] * B[k * DC + c];
    C[r * DC + c] = s;
}

// ======== L1: zero + (M3 = W4 @ fcW) ========
__global__ void k_zero(const float* __restrict__ W4, const float* __restrict__ fcW) {
    if (blockIdx.x < ZB) {
        int i = blockIdx.x * blockDim.x + threadIdx.x;
        if (i < NN) g_indeg[i] = 0;
        if (i < NG * DC) g_pool[i] = 0.0f;
        if (i < NG * 3) g_usum[i] = 0.0f;
    } else {
        mm_tile(W4, fcW, g_M3, blockIdx.x - ZB);
    }
}

// ======== L2: count (+rank) + (M2 = W3 @ M3) ========
__global__ void k_count(const int* __restrict__ ei, const float* __restrict__ W3) {
    if (blockIdx.x < CB) {
        int e = blockIdx.x * blockDim.x + threadIdx.x;
        if (e >= NE) return;
        g_rank[e] = atomicAdd(&g_indeg[ei[NE + e]], 1);
    } else {
        mm_tile(W3, g_M3, g_M2, blockIdx.x - CB);
    }
}

// ======== L3: per-block inclusive scan + (M1 = W2 @ M2) ========
__global__ void k_scan1(const float* __restrict__ W2) {
    if (blockIdx.x < SCAN_NB) {
        __shared__ int s[SCAN_BS];
        int i = blockIdx.x * SCAN_BS + threadIdx.x;
        int v = (i < NN) ? g_indeg[i] : 0;
        s[threadIdx.x] = v;
        __syncthreads();
#pragma unroll
        for (int off = 1; off < SCAN_BS; off <<= 1) {
            int t = (threadIdx.x >= off) ? s[threadIdx.x - off] : 0;
            __syncthreads();
            s[threadIdx.x] += t;
            __syncthreads();
        }
        if (i < NN) g_scan_tmp[i] = s[threadIdx.x];
        if (threadIdx.x == SCAN_BS - 1) g_bsum[blockIdx.x] = s[threadIdx.x];
    } else {
        mm_tile(W2, g_M2, g_M1, blockIdx.x - SCAN_NB);
    }
}

// ======== L4: rowptr + dinv + (Wc = W1 @ M1) ========
__global__ void k_scan3(const float* __restrict__ W1) {
    if (blockIdx.x < SCAN_NB) {
        __shared__ int sred[SCAN_BS];
        int partial = 0;
        for (int j = threadIdx.x; j < blockIdx.x; j += SCAN_BS) partial += g_bsum[j];
        sred[threadIdx.x] = partial;
        __syncthreads();
#pragma unroll
        for (int off = SCAN_BS / 2; off > 0; off >>= 1) {
            if (threadIdx.x < off) sred[threadIdx.x] += sred[threadIdx.x + off];
            __syncthreads();
        }
        int base = sred[0];
        int i = blockIdx.x * SCAN_BS + threadIdx.x;
        if (i < NN) {
            int d = g_indeg[i];
            g_rowptr[i] = base + g_scan_tmp[i] - d;
            g_dinv[i]   = rsqrtf((float)d + 1.0f);
        }
    } else {
        mm_tile(W1, g_M1, g_Wc, blockIdx.x - SCAN_NB);
    }
}

// ======== L5: gemmY (blocks [0,GYB)) + cvec (block GYB) + fill (rest) ========
// gemmY: Y0 = X @ Wc. fill: atomic-free via precomputed ranks.
__global__ __launch_bounds__(256) void k_fill_gemm(
    const float* __restrict__ X, const int* __restrict__ ei,
    const float* __restrict__ b1, const float* __restrict__ b2,
    const float* __restrict__ b3, const float* __restrict__ b4,
    const float* __restrict__ fcW)
{
    __shared__ float Ws[DD][DC];
    __shared__ float As[128][33];

    if (blockIdx.x < GYB) {
        int t  = threadIdx.x;
        int m0 = blockIdx.x * 128;
        int rb = t >> 3;                  // 0..31
        int cg = (t & 7) << 2;            // col group of 4

#pragma unroll
        for (int i = 0; i < 4; i++) {
            int lin = t + i * 256;
            int r = lin >> 3, c4 = (lin & 7) << 2;
            *(float4*)&Ws[r][c4] = *(const float4*)(g_Wc + r * DC + c4);
        }

        float4 ac[4];
#pragma unroll
        for (int j = 0; j < 4; j++) ac[j] = make_float4(0.f, 0.f, 0.f, 0.f);

        for (int k0 = 0; k0 < DD; k0 += 32) {
            __syncthreads();
#pragma unroll
            for (int i = 0; i < 4; i++) {
                int lin = t + i * 256;
                int r = lin >> 3, c4 = (lin & 7) << 2;
                int gr = m0 + r;
                float4 v = make_float4(0.f, 0.f, 0.f, 0.f);
                if (gr < NN) v = *(const float4*)(X + (size_t)gr * DD + k0 + c4);
                As[r][c4 + 0] = v.x; As[r][c4 + 1] = v.y;
                As[r][c4 + 2] = v.z; As[r][c4 + 3] = v.w;
            }
            __syncthreads();
#pragma unroll
            for (int k = 0; k < 32; k++) {
                float4 wv = *(const float4*)&Ws[k0 + k][cg];
#pragma unroll
                for (int j = 0; j < 4; j++) {
                    float a = As[rb + 32 * j][k];
                    ac[j].x += a * wv.x; ac[j].y += a * wv.y;
                    ac[j].z += a * wv.z; ac[j].w += a * wv.w;
                }
            }
        }
#pragma unroll
        for (int j = 0; j < 4; j++) {
            int gr = m0 + rb + 32 * j;
            if (gr < NN) *(float4*)(g_Y0 + (size_t)gr * DC + cg) = ac[j];
        }
    } else if (blockIdx.x == GYB) {
        // cvec: c_i = b_i^T M_i  (M4 = fcW)
        int t = threadIdx.x;
        if (t < 128) {
            int i = t >> 5, c = t & 31;
            const float* b = (i == 0) ? b1 : (i == 1) ? b2 : (i == 2) ? b3 : b4;
            const float* M = (i == 0) ? g_M1 : (i == 1) ? g_M2 : (i == 2) ? g_M3 : fcW;
            float s = 0.0f;
#pragma unroll 8
            for (int k = 0; k < DD; k++) s += b[k] * M[k * DC + c];
            g_cv[i * DC + c] = s;
        }
    } else {
        int e = (blockIdx.x - GYB - 1) * blockDim.x + threadIdx.x;
        if (e >= NE) return;
        int s = ei[e];
        int d = ei[NE + e];
        int pos = g_rowptr[d] + g_rank[e];
        g_csr[pos] = make_int2(s, __float_as_int(g_dinv[s] * g_dinv[d]));
    }
}

// ======== fused vector aggregate + block-specialized scalar u-chain ========
// Blocks [0, VB):      Yout = Â Yin   (clean loop)
// Blocks [VB, VB+UB):  u-chain stage (STAGE 1: 1->u1, 2: u1->u2, 3: u2->u3)
// STAGE 1,3: Y0->Y1 ;  STAGE 2,4: Y1->Y0.  Final result lands in g_Y0.
template <int STAGE>
__global__ __launch_bounds__(256) void k_vagg() {
    const float* __restrict__ Yin  = (STAGE == 1 || STAGE == 3) ? g_Y0 : g_Y1;
    float*       __restrict__ Yout = (STAGE == 1 || STAGE == 3) ? g_Y1 : g_Y0;

    if (blockIdx.x < VB) {
        int gid = blockIdx.x * blockDim.x + threadIdx.x;
        int n   = gid >> 5;
        if (n >= NN) return;
        int l = gid & 31;
        float dv  = g_dinv[n];
        float acc = dv * dv * Yin[(size_t)n * DC + l];
        int beg = g_rowptr[n], end = beg + g_indeg[n];
        int e = beg;
        for (; e + 8 <= end; e += 8) {
            int2 c0 = g_csr[e],     c1 = g_csr[e + 1];
            int2 c2 = g_csr[e + 2], c3 = g_csr[e + 3];
            int2 c4 = g_csr[e + 4], c5 = g_csr[e + 5];
            int2 c6 = g_csr[e + 6], c7 = g_csr[e + 7];
            float v0 = Yin[(size_t)c0.x * DC + l], v1 = Yin[(size_t)c1.x * DC + l];
            float v2 = Yin[(size_t)c2.x * DC + l], v3 = Yin[(size_t)c3.x * DC + l];
            float v4 = Yin[(size_t)c4.x * DC + l], v5 = Yin[(size_t)c5.x * DC + l];
            float v6 = Yin[(size_t)c6.x * DC + l], v7 = Yin[(size_t)c7.x * DC + l];
            acc += __int_as_float(c0.y) * v0 + __int_as_float(c1.y) * v1
                 + __int_as_float(c2.y) * v2 + __int_as_float(c3.y) * v3
                 + __int_as_float(c4.y) * v4 + __int_as_float(c5.y) * v5
                 + __int_as_float(c6.y) * v6 + __int_as_float(c7.y) * v7;
        }
        for (; e + 2 <= end; e += 2) {
            int2 c0 = g_csr[e], c1 = g_csr[e + 1];
            acc += __int_as_float(c0.y) * Yin[(size_t)c0.x * DC + l]
                 + __int_as_float(c1.y) * Yin[(size_t)c1.x * DC + l];
        }
        if (e < end) {
            int2 cv = g_csr[e];
            acc += __int_as_float(cv.y) * Yin[(size_t)cv.x * DC + l];
        }
        Yout[(size_t)n * DC + l] = acc;
    } else if (STAGE < 4) {
        // scalar u-chain stage (block-uniform path; clean loop)
        int n = (blockIdx.x - VB) * blockDim.x + threadIdx.x;
        if (n >= NN) return;
        const float* uin = (STAGE == 2) ? g_u1 : (STAGE == 3) ? g_u2 : nullptr;
        float*      uout = (STAGE == 1) ? g_u1 : (STAGE == 2) ? g_u2 : g_u3;
        float dv = g_dinv[n];
        float acc = (STAGE == 1) ? dv * dv : dv * dv * uin[n];
        int beg = g_rowptr[n], end = beg + g_indeg[n];
        if (STAGE == 1) {
            for (int e = beg; e < end; e++) acc += __int_as_float(g_csr[e].y);
        } else {
            for (int e = beg; e < end; e++) {
                int2 cv = g_csr[e];
                acc += __int_as_float(cv.y) * uin[cv.x];
            }
        }
        uout[n] = acc;
    }
}

// ======== pooled sums, fused: pool blocks [0,PB) + upool blocks [PB,PB+UPB) ====
#define POOL_CHUNK 16
__global__ __launch_bounds__(256) void k_pool(const int* __restrict__ batch) {
    if (blockIdx.x < PB) {
        int gid = blockIdx.x * blockDim.x + threadIdx.x;
        int w   = gid >> 5;
        int n0  = w * POOL_CHUNK;
        if (n0 >= NN) return;
        int l = gid & 31;
        int cur = batch[n0];
        float acc = 0.0f;
        for (int i = 0; i < POOL_CHUNK && n0 + i < NN; i++) {
            int n = n0 + i;
            int g = batch[n];
            if (g != cur) {
                atomicAdd(&g_pool[cur * DC + l], acc);
                acc = 0.0f; cur = g;
            }
            acc += g_Y0[(size_t)n * DC + l];   // final Z lives in g_Y0
        }
        atomicAdd(&g_pool[cur * DC + l], acc);
    } else {
        int t  = (blockIdx.x - PB) * blockDim.x + threadIdx.x;
        int n0 = t * POOL_CHUNK;
        if (n0 >= NN) return;
        int cur = batch[n0];
        float s1 = 0.f, s2 = 0.f, s3 = 0.f;
        for (int i = 0; i < POOL_CHUNK && n0 + i < NN; i++) {
            int n = n0 + i;
            int g = batch[n];
            if (g != cur) {
                atomicAdd(&g_usum[cur * 3 + 0], s1);
                atomicAdd(&g_usum[cur * 3 + 1], s2);
                atomicAdd(&g_usum[cur * 3 + 2], s3);
                s1 = s2 = s3 = 0.f; cur = g;
            }
            s1 += g_u1[n]; s2 += g_u2[n]; s3 += g_u3[n];
        }
        atomicAdd(&g_usum[cur * 3 + 0], s1);
        atomicAdd(&g_usum[cur * 3 + 1], s2);
        atomicAdd(&g_usum[cur * 3 + 2], s3);
    }
}

// ======== final: mean pool + rank-1 bias terms; cnt via binary search ========
__global__ void k_final(const int* __restrict__ batch,
                        const float* __restrict__ fcb, float* __restrict__ out) {
    int g = blockIdx.x;
    int c = threadIdx.x;   // 32
    int lo = 0, hi = NN;
    while (lo < hi) { int m = (lo + hi) >> 1; if (batch[m] < g) lo = m + 1; else hi = m; }
    int lo2 = lo, hi2 = NN;
    while (lo2 < hi2) { int m = (lo2 + hi2) >> 1; if (batch[m] <= g) lo2 = m + 1; else hi2 = m; }
    float cnt = (float)(lo2 - lo);

    float v = g_pool[g * DC + c]
            + g_usum[g * 3 + 2] * g_cv[0 * DC + c]      // u3 * (b1ᵀ W2W3W4 fcW)
            + g_usum[g * 3 + 1] * g_cv[1 * DC + c]      // u2 * (b2ᵀ W3W4 fcW)
            + g_usum[g * 3 + 0] * g_cv[2 * DC + c]      // u1 * (b3ᵀ W4 fcW)
            + cnt * (g_cv[3 * DC + c] + fcb[c]);        // 1  * (b4ᵀ fcW + fcb)
    out[g * DC + c] = v / fmaxf(cnt, 1.0f);
}

extern "C" void kernel_launch(void* const* d_in, const int* in_sizes, int n_in,
                              void* d_out, int out_size) {
    const float* x     = (const float*)d_in[0];
    const int*   ei    = (const int*)d_in[1];
    const int*   batch = (const int*)d_in[2];
    const float* W1 = (const float*)d_in[3];
    const float* b1 = (const float*)d_in[4];
    const float* W2 = (const float*)d_in[5];
    const float* b2 = (const float*)d_in[6];
    const float* W3 = (const float*)d_in[7];
    const float* b3 = (const float*)d_in[8];
    const float* W4 = (const float*)d_in[9];
    const float* b4 = (const float*)d_in[10];
    const float* fcW = (const float*)d_in[11];
    const float* fcb = (const float*)d_in[12];
    float* out = (float*)d_out;

    const int TB = 256;
    // prep chain with the weight chain riding as extra blocks
    k_zero <<<ZB + MMB, TB>>>(W4, fcW);            // zero + M3
    k_count<<<CB + MMB, TB>>>(ei, W3);             // count/rank + M2
    k_scan1<<<SCAN_NB + MMB, TB>>>(W2);            // scan + M1
    k_scan3<<<SCAN_NB + MMB, TB>>>(W1);            // rowptr/dinv + Wc
    k_fill_gemm<<<GYB + 1 + CB, TB>>>(x, ei, b1, b2, b3, b4, fcW);  // gemmY + cvec + fill

    // Â-powers with block-specialized u-chain riding along
    k_vagg<1><<<VB + UB, TB>>>();
    k_vagg<2><<<VB + UB, TB>>>();
    k_vagg<3><<<VB + UB, TB>>>();
    k_vagg<4><<<VB, TB>>>();

    // pooling (pool + upool fused) + final
    k_pool<<<PB + UPB, TB>>>(batch);
    k_final<<<NG, DC>>>(batch, fcb, out);
}

// round 14
// speedup vs baseline: 1.8835x; 1.0850x over previous
#include <cuda_runtime.h>
#include <cstddef>

#define NN 50000
#define NE 600000
#define DD 128
#define DC 32          // collapsed output width
#define NG 64

#define SCAN_BS 256
#define SCAN_NB ((NN + SCAN_BS - 1) / SCAN_BS)   // 196

#define VB 6250        // vector blocks per vagg (50000 warps)
#define UB SCAN_NB     // scalar-u blocks appended (196)

#define ZB  SCAN_NB                     // zero blocks
#define CB  ((NE + 255) / 256)          // count/fill blocks (2344)
#define MMB 16                          // blocks per 128x32 weight mm
#define GYB ((NN + 127) / 128)          // gemmY blocks (391)
#define PB  ((VB / 16) + 1)             // pool blocks
#define UPB ((NN / 16 + 255) / 256)     // upool blocks (13)

// -------- scratch (device globals; never passed as kernel args from host) --------
__device__ int   g_indeg[NN];
__device__ float g_dinv[NN];
__device__ int   g_rowptr[NN];
__device__ int   g_rank[NE];           // per-edge slot within dst segment
__device__ int   g_scan_tmp[NN];
__device__ int   g_bsum[SCAN_NB];
__device__ __align__(8) int2 g_csr[NE];    // (src, __float_as_int(norm)), node-ordered rows
__device__ float g_u1[NN], g_u2[NN], g_u3[NN];
__device__ __align__(16) float g_M1[DD * DC];
__device__ __align__(16) float g_M2[DD * DC];
__device__ __align__(16) float g_M3[DD * DC];
__device__ __align__(16) float g_Wc[DD * DC];
__device__ float g_cv[4 * DC];
__device__ __align__(16) float g_Y0[(size_t)NN * DC];
__device__ __align__(16) float g_Y1[(size_t)NN * DC];
__device__ float g_pool[NG * DC];
__device__ float g_usum[NG * 3];

// ======== mm tile with smem-staged B and float4 A reads ========
// C[128,32] = A[128,128] @ B[128,32]; 16 rider blocks, blk in [0,16)
__device__ __forceinline__ void mm_tile(const float* __restrict__ A,
                                        const float* __restrict__ B,
                                        float* __restrict__ C, int blk) {
    __shared__ float Bs[DD][DC];     // 16 KB
    int t = threadIdx.x;
#pragma unroll
    for (int i = 0; i < 4; i++) {
        int lin = t + i * 256;       // 1024 float4 slots
        int r = lin >> 3, c4 = (lin & 7) << 2;
        *(float4*)&Bs[r][c4] = *(const float4*)(B + r * DC + c4);
    }
    __syncthreads();
    int idx = blk * 256 + t;
    int r = idx >> 5, c = idx & 31;
    float s = 0.0f;
#pragma unroll
    for (int k4 = 0; k4 < DD; k4 += 4) {
        float4 a = *(const float4*)(A + r * DD + k4);
        s += a.x * Bs[k4][c] + a.y * Bs[k4 + 1][c]
           + a.z * Bs[k4 + 2][c] + a.w * Bs[k4 + 3][c];
    }
    C[r * DC + c] = s;
}

// ======== L1: zero + (M3 = W4 @ fcW) ========
__global__ void k_zero(const float* __restrict__ W4, const float* __restrict__ fcW) {
    if (blockIdx.x < ZB) {
        int i = blockIdx.x * blockDim.x + threadIdx.x;
        if (i < NN) g_indeg[i] = 0;
        if (i < NG * DC) g_pool[i] = 0.0f;
        if (i < NG * 3) g_usum[i] = 0.0f;
    } else {
        mm_tile(W4, fcW, g_M3, blockIdx.x - ZB);
    }
}

// ======== L2: count (+rank) + (M2 = W3 @ M3) ========
__global__ void k_count(const int* __restrict__ ei, const float* __restrict__ W3) {
    if (blockIdx.x < CB) {
        int e = blockIdx.x * blockDim.x + threadIdx.x;
        if (e >= NE) return;
        g_rank[e] = atomicAdd(&g_indeg[ei[NE + e]], 1);
    } else {
        mm_tile(W3, g_M3, g_M2, blockIdx.x - CB);
    }
}

// ======== L3: per-block inclusive scan + (M1 = W2 @ M2) ========
__global__ void k_scan1(const float* __restrict__ W2) {
    if (blockIdx.x < SCAN_NB) {
        __shared__ int s[SCAN_BS];
        int i = blockIdx.x * SCAN_BS + threadIdx.x;
        int v = (i < NN) ? g_indeg[i] : 0;
        s[threadIdx.x] = v;
        __syncthreads();
#pragma unroll
        for (int off = 1; off < SCAN_BS; off <<= 1) {
            int t = (threadIdx.x >= off) ? s[threadIdx.x - off] : 0;
            __syncthreads();
            s[threadIdx.x] += t;
            __syncthreads();
        }
        if (i < NN) g_scan_tmp[i] = s[threadIdx.x];
        if (threadIdx.x == SCAN_BS - 1) g_bsum[blockIdx.x] = s[threadIdx.x];
    } else {
        mm_tile(W2, g_M2, g_M1, blockIdx.x - SCAN_NB);
    }
}

// ======== L4: rowptr + dinv + (Wc = W1 @ M1) ========
__global__ void k_scan3(const float* __restrict__ W1) {
    if (blockIdx.x < SCAN_NB) {
        __shared__ int sred[SCAN_BS];
        int partial = 0;
        for (int j = threadIdx.x; j < blockIdx.x; j += SCAN_BS) partial += g_bsum[j];
        sred[threadIdx.x] = partial;
        __syncthreads();
#pragma unroll
        for (int off = SCAN_BS / 2; off > 0; off >>= 1) {
            if (threadIdx.x < off) sred[threadIdx.x] += sred[threadIdx.x + off];
            __syncthreads();
        }
        int base = sred[0];
        int i = blockIdx.x * SCAN_BS + threadIdx.x;
        if (i < NN) {
            int d = g_indeg[i];
            g_rowptr[i] = base + g_scan_tmp[i] - d;
            g_dinv[i]   = rsqrtf((float)d + 1.0f);
        }
    } else {
        mm_tile(W1, g_M1, g_Wc, blockIdx.x - SCAN_NB);
    }
}

// ======== L5: gemmY (blocks [0,GYB)) + cvec (block GYB) + fill (rest) ========
__global__ __launch_bounds__(256) void k_fill_gemm(
    const float* __restrict__ X, const int* __restrict__ ei,
    const float* __restrict__ b1, const float* __restrict__ b2,
    const float* __restrict__ b3, const float* __restrict__ b4,
    const float* __restrict__ fcW)
{
    __shared__ float Ws[DD][DC];
    __shared__ float As[128][33];

    if (blockIdx.x < GYB) {
        int t  = threadIdx.x;
        int m0 = blockIdx.x * 128;
        int rb = t >> 3;                  // 0..31
        int cg = (t & 7) << 2;            // col group of 4

#pragma unroll
        for (int i = 0; i < 4; i++) {
            int lin = t + i * 256;
            int r = lin >> 3, c4 = (lin & 7) << 2;
            *(float4*)&Ws[r][c4] = *(const float4*)(g_Wc + r * DC + c4);
        }

        float4 ac[4];
#pragma unroll
        for (int j = 0; j < 4; j++) ac[j] = make_float4(0.f, 0.f, 0.f, 0.f);

        for (int k0 = 0; k0 < DD; k0 += 32) {
            __syncthreads();
#pragma unroll
            for (int i = 0; i < 4; i++) {
                int lin = t + i * 256;
                int r = lin >> 3, c4 = (lin & 7) << 2;
                int gr = m0 + r;
                float4 v = make_float4(0.f, 0.f, 0.f, 0.f);
                if (gr < NN) v = *(const float4*)(X + (size_t)gr * DD + k0 + c4);
                As[r][c4 + 0] = v.x; As[r][c4 + 1] = v.y;
                As[r][c4 + 2] = v.z; As[r][c4 + 3] = v.w;
            }
            __syncthreads();
#pragma unroll
            for (int k = 0; k < 32; k++) {
                float4 wv = *(const float4*)&Ws[k0 + k][cg];
#pragma unroll
                for (int j = 0; j < 4; j++) {
                    float a = As[rb + 32 * j][k];
                    ac[j].x += a * wv.x; ac[j].y += a * wv.y;
                    ac[j].z += a * wv.z; ac[j].w += a * wv.w;
                }
            }
        }
#pragma unroll
        for (int j = 0; j < 4; j++) {
            int gr = m0 + rb + 32 * j;
            if (gr < NN) *(float4*)(g_Y0 + (size_t)gr * DC + cg) = ac[j];
        }
    } else if (blockIdx.x == GYB) {
        int t = threadIdx.x;
        if (t < 128) {
            int i = t >> 5, c = t & 31;
            const float* b = (i == 0) ? b1 : (i == 1) ? b2 : (i == 2) ? b3 : b4;
            const float* M = (i == 0) ? g_M1 : (i == 1) ? g_M2 : (i == 2) ? g_M3 : fcW;
            float s = 0.0f;
#pragma unroll 8
            for (int k = 0; k < DD; k++) s += b[k] * M[k * DC + c];
            g_cv[i * DC + c] = s;
        }
    } else {
        int e = (blockIdx.x - GYB - 1) * blockDim.x + threadIdx.x;
        if (e >= NE) return;
        int s = ei[e];
        int d = ei[NE + e];
        int pos = g_rowptr[d] + g_rank[e];
        g_csr[pos] = make_int2(s, __float_as_int(g_dinv[s] * g_dinv[d]));
    }
}

// ======== vector aggregate: warp per node, 4 edges per LDG.128 ========
// Lane layout: grp = lane>>3 handles edge e+grp; lane covers 4 cols (float4).
// After the loop, cross-group shuffle reduction; group 0 adds self term + stores.
// Blocks [VB, VB+UB): scalar u-chain stage (unchanged).
template <int STAGE>
__global__ __launch_bounds__(256) void k_vagg() {
    const float* __restrict__ Yin  = (STAGE == 1 || STAGE == 3) ? g_Y0 : g_Y1;
    float*       __restrict__ Yout = (STAGE == 1 || STAGE == 3) ? g_Y1 : g_Y0;

    if (blockIdx.x < VB) {
        int gid  = blockIdx.x * blockDim.x + threadIdx.x;
        int n    = gid >> 5;
        if (n >= NN) return;
        int lane = gid & 31;
        int grp  = lane >> 3;            // 0..3
        int cg   = (lane & 7) << 2;      // col*4

        int beg = g_rowptr[n], end = beg + g_indeg[n];
        float4 acc = make_float4(0.f, 0.f, 0.f, 0.f);

        for (int e = beg; e < end; e += 4) {
            int ee = e + grp;
            int2 cv = (ee < end) ? g_csr[ee] : make_int2(0, 0);
            float w = __int_as_float(cv.y);        // 0 for tail -> contributes 0
            float4 v = *(const float4*)(Yin + (size_t)cv.x * DC + cg);
            acc.x += w * v.x; acc.y += w * v.y;
            acc.z += w * v.z; acc.w += w * v.w;
        }
        // reduce across the 4 edge-groups (lanes l, l+8, l+16, l+24)
#pragma unroll
        for (int off = 8; off <= 16; off <<= 1) {
            acc.x += __shfl_xor_sync(0xffffffffu, acc.x, off);
            acc.y += __shfl_xor_sync(0xffffffffu, acc.y, off);
            acc.z += __shfl_xor_sync(0xffffffffu, acc.z, off);
            acc.w += __shfl_xor_sync(0xffffffffu, acc.w, off);
        }
        if (grp == 0) {
            float dv = g_dinv[n];
            float sn = dv * dv;
            float4 self = *(const float4*)(Yin + (size_t)n * DC + cg);
            acc.x += sn * self.x; acc.y += sn * self.y;
            acc.z += sn * self.z; acc.w += sn * self.w;
            *(float4*)(Yout + (size_t)n * DC + cg) = acc;
        }
    } else if (STAGE < 4) {
        // scalar u-chain stage (block-uniform path; clean loop)
        int n = (blockIdx.x - VB) * blockDim.x + threadIdx.x;
        if (n >= NN) return;
        const float* uin = (STAGE == 2) ? g_u1 : (STAGE == 3) ? g_u2 : nullptr;
        float*      uout = (STAGE == 1) ? g_u1 : (STAGE == 2) ? g_u2 : g_u3;
        float dv = g_dinv[n];
        float acc = (STAGE == 1) ? dv * dv : dv * dv * uin[n];
        int beg = g_rowptr[n], end = beg + g_indeg[n];
        if (STAGE == 1) {
            for (int e = beg; e < end; e++) acc += __int_as_float(g_csr[e].y);
        } else {
            for (int e = beg; e < end; e++) {
                int2 cv = g_csr[e];
                acc += __int_as_float(cv.y) * uin[cv.x];
            }
        }
        uout[n] = acc;
    }
}

// ======== pooled sums, fused: pool blocks [0,PB) + upool blocks [PB,PB+UPB) ====
#define POOL_CHUNK 16
__global__ __launch_bounds__(256) void k_pool(const int* __restrict__ batch) {
    if (blockIdx.x < PB) {
        int gid = blockIdx.x * blockDim.x + threadIdx.x;
        int w   = gid >> 5;
        int n0  = w * POOL_CHUNK;
        if (n0 >= NN) return;
        int l = gid & 31;
        int cur = batch[n0];
        float acc = 0.0f;
        for (int i = 0; i < POOL_CHUNK && n0 + i < NN; i++) {
            int n = n0 + i;
            int g = batch[n];
            if (g != cur) {
                atomicAdd(&g_pool[cur * DC + l], acc);
                acc = 0.0f; cur = g;
            }
            acc += g_Y0[(size_t)n * DC + l];   // final Z lives in g_Y0
        }
        atomicAdd(&g_pool[cur * DC + l], acc);
    } else {
        int t  = (blockIdx.x - PB) * blockDim.x + threadIdx.x;
        int n0 = t * POOL_CHUNK;
        if (n0 >= NN) return;
        int cur = batch[n0];
        float s1 = 0.f, s2 = 0.f, s3 = 0.f;
        for (int i = 0; i < POOL_CHUNK && n0 + i < NN; i++) {
            int n = n0 + i;
            int g = batch[n];
            if (g != cur) {
                atomicAdd(&g_usum[cur * 3 + 0], s1);
                atomicAdd(&g_usum[cur * 3 + 1], s2);
                atomicAdd(&g_usum[cur * 3 + 2], s3);
                s1 = s2 = s3 = 0.f; cur = g;
            }
            s1 += g_u1[n]; s2 += g_u2[n]; s3 += g_u3[n];
        }
        atomicAdd(&g_usum[cur * 3 + 0], s1);
        atomicAdd(&g_usum[cur * 3 + 1], s2);
        atomicAdd(&g_usum[cur * 3 + 2], s3);
    }
}

// ======== final: mean pool + rank-1 bias terms; cnt via binary search ========
__global__ void k_final(const int* __restrict__ batch,
                        const float* __restrict__ fcb, float* __restrict__ out) {
    int g = blockIdx.x;
    int c = threadIdx.x;   // 32
    int lo = 0, hi = NN;
    while (lo < hi) { int m = (lo + hi) >> 1; if (batch[m] < g) lo = m + 1; else hi = m; }
    int lo2 = lo, hi2 = NN;
    while (lo2 < hi2) { int m = (lo2 + hi2) >> 1; if (batch[m] <= g) lo2 = m + 1; else hi2 = m; }
    float cnt = (float)(lo2 - lo);

    float v = g_pool[g * DC + c]
            + g_usum[g * 3 + 2] * g_cv[0 * DC + c]      // u3 * (b1ᵀ W2W3W4 fcW)
            + g_usum[g * 3 + 1] * g_cv[1 * DC + c]      // u2 * (b2ᵀ W3W4 fcW)
            + g_usum[g * 3 + 0] * g_cv[2 * DC + c]      // u1 * (b3ᵀ W4 fcW)
            + cnt * (g_cv[3 * DC + c] + fcb[c]);        // 1  * (b4ᵀ fcW + fcb)
    out[g * DC + c] = v / fmaxf(cnt, 1.0f);
}

extern "C" void kernel_launch(void* const* d_in, const int* in_sizes, int n_in,
                              void* d_out, int out_size) {
    const float* x     = (const float*)d_in[0];
    const int*   ei    = (const int*)d_in[1];
    const int*   batch = (const int*)d_in[2];
    const float* W1 = (const float*)d_in[3];
    const float* b1 = (const float*)d_in[4];
    const float* W2 = (const float*)d_in[5];
    const float* b2 = (const float*)d_in[6];
    const float* W3 = (const float*)d_in[7];
    const float* b3 = (const float*)d_in[8];
    const float* W4 = (const float*)d_in[9];
    const float* b4 = (const float*)d_in[10];
    const float* fcW = (const float*)d_in[11];
    const float* fcb = (const float*)d_in[12];
    float* out = (float*)d_out;

    const int TB = 256;
    // prep chain with the weight chain riding as extra blocks
    k_zero <<<ZB + MMB, TB>>>(W4, fcW);            // zero + M3
    k_count<<<CB + MMB, TB>>>(ei, W3);             // count/rank + M2
    k_scan1<<<SCAN_NB + MMB, TB>>>(W2);            // scan + M1
    k_scan3<<<SCAN_NB + MMB, TB>>>(W1);            // rowptr/dinv + Wc
    k_fill_gemm<<<GYB + 1 + CB, TB>>>(x, ei, b1, b2, b3, b4, fcW);  // gemmY + cvec + fill

    // Â-powers with block-specialized u-chain riding along
    k_vagg<1><<<VB + UB, TB>>>();
    k_vagg<2><<<VB + UB, TB>>>();
    k_vagg<3><<<VB + UB, TB>>>();
    k_vagg<4><<<VB, TB>>>();

    // pooling (pool + upool fused) + final
    k_pool<<<PB + UPB, TB>>>(batch);
    k_final<<<NG, DC>>>(batch, fcb, out);
}

// round 15
// speedup vs baseline: 1.9829x; 1.0528x over previous
#include <cuda_runtime.h>
#include <cuda_fp16.h>
#include <cstddef>

#define NN 50000
#define NE 600000
#define DD 128
#define DC 32          // collapsed output width
#define NG 64

#define SCAN_BS 256
#define SCAN_NB ((NN + SCAN_BS - 1) / SCAN_BS)   // 196

#define VB 6250        // vector blocks per vagg (50000 warps)
#define UB SCAN_NB     // scalar-u blocks appended (196)

#define ZB  SCAN_NB                     // zero blocks
#define CB  ((NE + 255) / 256)          // count/fill blocks (2344)
#define MMB 16                          // blocks per 128x32 weight mm
#define GYB ((NN + 127) / 128)          // gemmY blocks (391)
#define PB  ((VB / 16) + 1)             // pool blocks
#define UPB ((NN / 16 + 255) / 256)     // upool blocks (13)

// -------- scratch (device globals; never passed as kernel args from host) --------
__device__ int   g_indeg[NN];
__device__ float g_dinv[NN];
__device__ int   g_rowptr[NN];
__device__ int   g_rank[NE];           // per-edge slot within dst segment
__device__ int   g_scan_tmp[NN];
__device__ int   g_bsum[SCAN_NB];
__device__ __align__(8) int2 g_csr[NE];    // (src, __float_as_int(norm)), node-ordered rows
__device__ float g_u1[NN], g_u2[NN], g_u3[NN];
__device__ __align__(16) float g_M1[DD * DC];
__device__ __align__(16) float g_M2[DD * DC];
__device__ __align__(16) float g_M3[DD * DC];
__device__ __align__(16) float g_Wc[DD * DC];
__device__ float g_cv[4 * DC];
__device__ __align__(16) __half g_Yh0[(size_t)NN * DC];   // fp16 Y ping-pong
__device__ __align__(16) __half g_Yh1[(size_t)NN * DC];
__device__ float g_pool[NG * DC];
__device__ float g_usum[NG * 3];

// pack float4 -> 2x half2 (as uint2)
__device__ __forceinline__ uint2 pack_h4(float4 a) {
    __half2 h0 = __floats2half2_rn(a.x, a.y);
    __half2 h1 = __floats2half2_rn(a.z, a.w);
    uint2 r;
    r.x = *reinterpret_cast<unsigned*>(&h0);
    r.y = *reinterpret_cast<unsigned*>(&h1);
    return r;
}
__device__ __forceinline__ float4 unpack_h4(uint2 r) {
    __half2 h0 = *reinterpret_cast<__half2*>(&r.x);
    __half2 h1 = *reinterpret_cast<__half2*>(&r.y);
    float2 f0 = __half22float2(h0);
    float2 f1 = __half22float2(h1);
    return make_float4(f0.x, f0.y, f1.x, f1.y);
}

// ======== mm tile with smem-staged B and float4 A reads ========
__device__ __forceinline__ void mm_tile(const float* __restrict__ A,
                                        const float* __restrict__ B,
                                        float* __restrict__ C, int blk) {
    __shared__ float Bs[DD][DC];     // 16 KB
    int t = threadIdx.x;
#pragma unroll
    for (int i = 0; i < 4; i++) {
        int lin = t + i * 256;       // 1024 float4 slots
        int r = lin >> 3, c4 = (lin & 7) << 2;
        *(float4*)&Bs[r][c4] = *(const float4*)(B + r * DC + c4);
    }
    __syncthreads();
    int idx = blk * 256 + t;
    int r = idx >> 5, c = idx & 31;
    float s = 0.0f;
#pragma unroll
    for (int k4 = 0; k4 < DD; k4 += 4) {
        float4 a = *(const float4*)(A + r * DD + k4);
        s += a.x * Bs[k4][c] + a.y * Bs[k4 + 1][c]
           + a.z * Bs[k4 + 2][c] + a.w * Bs[k4 + 3][c];
    }
    C[r * DC + c] = s;
}

// ======== L1: zero + (M3 = W4 @ fcW) ========
__global__ void k_zero(const float* __restrict__ W4, const float* __restrict__ fcW) {
    if (blockIdx.x < ZB) {
        int i = blockIdx.x * blockDim.x + threadIdx.x;
        if (i < NN) g_indeg[i] = 0;
        if (i < NG * DC) g_pool[i] = 0.0f;
        if (i < NG * 3) g_usum[i] = 0.0f;
    } else {
        mm_tile(W4, fcW, g_M3, blockIdx.x - ZB);
    }
}

// ======== L2: count (+rank) + (M2 = W3 @ M3) ========
__global__ void k_count(const int* __restrict__ ei, const float* __restrict__ W3) {
    if (blockIdx.x < CB) {
        int e = blockIdx.x * blockDim.x + threadIdx.x;
        if (e >= NE) return;
        g_rank[e] = atomicAdd(&g_indeg[ei[NE + e]], 1);
    } else {
        mm_tile(W3, g_M3, g_M2, blockIdx.x - CB);
    }
}

// ======== L3: per-block inclusive scan + (M1 = W2 @ M2) ========
__global__ void k_scan1(const float* __restrict__ W2) {
    if (blockIdx.x < SCAN_NB) {
        __shared__ int s[SCAN_BS];
        int i = blockIdx.x * SCAN_BS + threadIdx.x;
        int v = (i < NN) ? g_indeg[i] : 0;
        s[threadIdx.x] = v;
        __syncthreads();
#pragma unroll
        for (int off = 1; off < SCAN_BS; off <<= 1) {
            int t = (threadIdx.x >= off) ? s[threadIdx.x - off] : 0;
            __syncthreads();
            s[threadIdx.x] += t;
            __syncthreads();
        }
        if (i < NN) g_scan_tmp[i] = s[threadIdx.x];
        if (threadIdx.x == SCAN_BS - 1) g_bsum[blockIdx.x] = s[threadIdx.x];
    } else {
        mm_tile(W2, g_M2, g_M1, blockIdx.x - SCAN_NB);
    }
}

// ======== L4: rowptr + dinv + (Wc = W1 @ M1) ========
__global__ void k_scan3(const float* __restrict__ W1) {
    if (blockIdx.x < SCAN_NB) {
        __shared__ int sred[SCAN_BS];
        int partial = 0;
        for (int j = threadIdx.x; j < blockIdx.x; j += SCAN_BS) partial += g_bsum[j];
        sred[threadIdx.x] = partial;
        __syncthreads();
#pragma unroll
        for (int off = SCAN_BS / 2; off > 0; off >>= 1) {
            if (threadIdx.x < off) sred[threadIdx.x] += sred[threadIdx.x + off];
            __syncthreads();
        }
        int base = sred[0];
        int i = blockIdx.x * SCAN_BS + threadIdx.x;
        if (i < NN) {
            int d = g_indeg[i];
            g_rowptr[i] = base + g_scan_tmp[i] - d;
            g_dinv[i]   = rsqrtf((float)d + 1.0f);
        }
    } else {
        mm_tile(W1, g_M1, g_Wc, blockIdx.x - SCAN_NB);
    }
}

// ======== L5: gemmY (blocks [0,GYB)) + cvec (block GYB) + fill (rest) ========
__global__ __launch_bounds__(256) void k_fill_gemm(
    const float* __restrict__ X, const int* __restrict__ ei,
    const float* __restrict__ b1, const float* __restrict__ b2,
    const float* __restrict__ b3, const float* __restrict__ b4,
    const float* __restrict__ fcW)
{
    __shared__ float Ws[DD][DC];
    __shared__ float As[128][33];

    if (blockIdx.x < GYB) {
        int t  = threadIdx.x;
        int m0 = blockIdx.x * 128;
        int rb = t >> 3;                  // 0..31
        int cg = (t & 7) << 2;            // col group of 4

#pragma unroll
        for (int i = 0; i < 4; i++) {
            int lin = t + i * 256;
            int r = lin >> 3, c4 = (lin & 7) << 2;
            *(float4*)&Ws[r][c4] = *(const float4*)(g_Wc + r * DC + c4);
        }

        float4 ac[4];
#pragma unroll
        for (int j = 0; j < 4; j++) ac[j] = make_float4(0.f, 0.f, 0.f, 0.f);

        for (int k0 = 0; k0 < DD; k0 += 32) {
            __syncthreads();
#pragma unroll
            for (int i = 0; i < 4; i++) {
                int lin = t + i * 256;
                int r = lin >> 3, c4 = (lin & 7) << 2;
                int gr = m0 + r;
                float4 v = make_float4(0.f, 0.f, 0.f, 0.f);
                if (gr < NN) v = *(const float4*)(X + (size_t)gr * DD + k0 + c4);
                As[r][c4 + 0] = v.x; As[r][c4 + 1] = v.y;
                As[r][c4 + 2] = v.z; As[r][c4 + 3] = v.w;
            }
            __syncthreads();
#pragma unroll
            for (int k = 0; k < 32; k++) {
                float4 wv = *(const float4*)&Ws[k0 + k][cg];
#pragma unroll
                for (int j = 0; j < 4; j++) {
                    float a = As[rb + 32 * j][k];
                    ac[j].x += a * wv.x; ac[j].y += a * wv.y;
                    ac[j].z += a * wv.z; ac[j].w += a * wv.w;
                }
            }
        }
#pragma unroll
        for (int j = 0; j < 4; j++) {
            int gr = m0 + rb + 32 * j;
            if (gr < NN)
                *(uint2*)(g_Yh0 + (size_t)gr * DC + cg) = pack_h4(ac[j]);
        }
    } else if (blockIdx.x == GYB) {
        int t = threadIdx.x;
        if (t < 128) {
            int i = t >> 5, c = t & 31;
            const float* b = (i == 0) ? b1 : (i == 1) ? b2 : (i == 2) ? b3 : b4;
            const float* M = (i == 0) ? g_M1 : (i == 1) ? g_M2 : (i == 2) ? g_M3 : fcW;
            float s = 0.0f;
#pragma unroll 8
            for (int k = 0; k < DD; k++) s += b[k] * M[k * DC + c];
            g_cv[i * DC + c] = s;
        }
    } else {
        int e = (blockIdx.x - GYB - 1) * blockDim.x + threadIdx.x;
        if (e >= NE) return;
        int s = ei[e];
        int d = ei[NE + e];
        int pos = g_rowptr[d] + g_rank[e];
        g_csr[pos] = make_int2(s, __float_as_int(g_dinv[s] * g_dinv[d]));
    }
}

// ======== vector aggregate (fp16 payload): warp per node, 4 edges/iter ========
// grp = lane>>3 handles edge e+grp; lane covers 4 cols via uint2 (2x half2).
// fp32 accumulate; fp16 store. Blocks [VB, VB+UB): scalar u-chain (fp32).
template <int STAGE>
__global__ __launch_bounds__(256) void k_vagg() {
    const __half* __restrict__ Yin  = (STAGE == 1 || STAGE == 3) ? g_Yh0 : g_Yh1;
    __half*       __restrict__ Yout = (STAGE == 1 || STAGE == 3) ? g_Yh1 : g_Yh0;

    if (blockIdx.x < VB) {
        int gid  = blockIdx.x * blockDim.x + threadIdx.x;
        int n    = gid >> 5;
        if (n >= NN) return;
        int lane = gid & 31;
        int grp  = lane >> 3;            // 0..3
        int cg   = (lane & 7) << 2;      // col*4

        int beg = g_rowptr[n], end = beg + g_indeg[n];
        float4 acc = make_float4(0.f, 0.f, 0.f, 0.f);

        for (int e = beg; e < end; e += 4) {
            int ee = e + grp;
            int2 cv = (ee < end) ? g_csr[ee] : make_int2(0, 0);
            float w = __int_as_float(cv.y);        // 0 for tail -> contributes 0
            float4 v = unpack_h4(*(const uint2*)(Yin + (size_t)cv.x * DC + cg));
            acc.x += w * v.x; acc.y += w * v.y;
            acc.z += w * v.z; acc.w += w * v.w;
        }
#pragma unroll
        for (int off = 8; off <= 16; off <<= 1) {
            acc.x += __shfl_xor_sync(0xffffffffu, acc.x, off);
            acc.y += __shfl_xor_sync(0xffffffffu, acc.y, off);
            acc.z += __shfl_xor_sync(0xffffffffu, acc.z, off);
            acc.w += __shfl_xor_sync(0xffffffffu, acc.w, off);
        }
        if (grp == 0) {
            float dv = g_dinv[n];
            float sn = dv * dv;
            float4 self = unpack_h4(*(const uint2*)(Yin + (size_t)n * DC + cg));
            acc.x += sn * self.x; acc.y += sn * self.y;
            acc.z += sn * self.z; acc.w += sn * self.w;
            *(uint2*)(Yout + (size_t)n * DC + cg) = pack_h4(acc);
        }
    } else if (STAGE < 4) {
        int n = (blockIdx.x - VB) * blockDim.x + threadIdx.x;
        if (n >= NN) return;
        const float* uin = (STAGE == 2) ? g_u1 : (STAGE == 3) ? g_u2 : nullptr;
        float*      uout = (STAGE == 1) ? g_u1 : (STAGE == 2) ? g_u2 : g_u3;
        float dv = g_dinv[n];
        float acc = (STAGE == 1) ? dv * dv : dv * dv * uin[n];
        int beg = g_rowptr[n], end = beg + g_indeg[n];
        if (STAGE == 1) {
            for (int e = beg; e < end; e++) acc += __int_as_float(g_csr[e].y);
        } else {
            for (int e = beg; e < end; e++) {
                int2 cv = g_csr[e];
                acc += __int_as_float(cv.y) * uin[cv.x];
            }
        }
        uout[n] = acc;
    }
}

// ======== pooled sums, fused: pool blocks [0,PB) + upool blocks [PB,PB+UPB) ====
#define POOL_CHUNK 16
__global__ __launch_bounds__(256) void k_pool(const int* __restrict__ batch) {
    if (blockIdx.x < PB) {
        int gid = blockIdx.x * blockDim.x + threadIdx.x;
        int w   = gid >> 5;
        int n0  = w * POOL_CHUNK;
        if (n0 >= NN) return;
        int l = gid & 31;
        int cur = batch[n0];
        float acc = 0.0f;
        for (int i = 0; i < POOL_CHUNK && n0 + i < NN; i++) {
            int n = n0 + i;
            int g = batch[n];
            if (g != cur) {
                atomicAdd(&g_pool[cur * DC + l], acc);
                acc = 0.0f; cur = g;
            }
            acc += __half2float(g_Yh0[(size_t)n * DC + l]);  // final Z in g_Yh0
        }
        atomicAdd(&g_pool[cur * DC + l], acc);
    } else {
        int t  = (blockIdx.x - PB) * blockDim.x + threadIdx.x;
        int n0 = t * POOL_CHUNK;
        if (n0 >= NN) return;
        int cur = batch[n0];
        float s1 = 0.f, s2 = 0.f, s3 = 0.f;
        for (int i = 0; i < POOL_CHUNK && n0 + i < NN; i++) {
            int n = n0 + i;
            int g = batch[n];
            if (g != cur) {
                atomicAdd(&g_usum[cur * 3 + 0], s1);
                atomicAdd(&g_usum[cur * 3 + 1], s2);
                atomicAdd(&g_usum[cur * 3 + 2], s3);
                s1 = s2 = s3 = 0.f; cur = g;
            }
            s1 += g_u1[n]; s2 += g_u2[n]; s3 += g_u3[n];
        }
        atomicAdd(&g_usum[cur * 3 + 0], s1);
        atomicAdd(&g_usum[cur * 3 + 1], s2);
        atomicAdd(&g_usum[cur * 3 + 2], s3);
    }
}

// ======== final: mean pool + rank-1 bias terms; cnt via binary search ========
__global__ void k_final(const int* __restrict__ batch,
                        const float* __restrict__ fcb, float* __restrict__ out) {
    int g = blockIdx.x;
    int c = threadIdx.x;   // 32
    int lo = 0, hi = NN;
    while (lo < hi) { int m = (lo + hi) >> 1; if (batch[m] < g) lo = m + 1; else hi = m; }
    int lo2 = lo, hi2 = NN;
    while (lo2 < hi2) { int m = (lo2 + hi2) >> 1; if (batch[m] <= g) lo2 = m + 1; else hi2 = m; }
    float cnt = (float)(lo2 - lo);

    float v = g_pool[g * DC + c]
            + g_usum[g * 3 + 2] * g_cv[0 * DC + c]      // u3 * (b1ᵀ W2W3W4 fcW)
            + g_usum[g * 3 + 1] * g_cv[1 * DC + c]      // u2 * (b2ᵀ W3W4 fcW)
            + g_usum[g * 3 + 0] * g_cv[2 * DC + c]      // u1 * (b3ᵀ W4 fcW)
            + cnt * (g_cv[3 * DC + c] + fcb[c]);        // 1  * (b4ᵀ fcW + fcb)
    out[g * DC + c] = v / fmaxf(cnt, 1.0f);
}

extern "C" void kernel_launch(void* const* d_in, const int* in_sizes, int n_in,
                              void* d_out, int out_size) {
    const float* x     = (const float*)d_in[0];
    const int*   ei    = (const int*)d_in[1];
    const int*   batch = (const int*)d_in[2];
    const float* W1 = (const float*)d_in[3];
    const float* b1 = (const float*)d_in[4];
    const float* W2 = (const float*)d_in[5];
    const float* b2 = (const float*)d_in[6];
    const float* W3 = (const float*)d_in[7];
    const float* b3 = (const float*)d_in[8];
    const float* W4 = (const float*)d_in[9];
    const float* b4 = (const float*)d_in[10];
    const float* fcW = (const float*)d_in[11];
    const float* fcb = (const float*)d_in[12];
    float* out = (float*)d_out;

    const int TB = 256;
    // prep chain with the weight chain riding as extra blocks
    k_zero <<<ZB + MMB, TB>>>(W4, fcW);            // zero + M3
    k_count<<<CB + MMB, TB>>>(ei, W3);             // count/rank + M2
    k_scan1<<<SCAN_NB + MMB, TB>>>(W2);            // scan + M1
    k_scan3<<<SCAN_NB + MMB, TB>>>(W1);            // rowptr/dinv + Wc
    k_fill_gemm<<<GYB + 1 + CB, TB>>>(x, ei, b1, b2, b3, b4, fcW);  // gemmY + cvec + fill

    // Â-powers (fp16 payload) with block-specialized u-chain riding along
    k_vagg<1><<<VB + UB, TB>>>();
    k_vagg<2><<<VB + UB, TB>>>();
    k_vagg<3><<<VB + UB, TB>>>();
    k_vagg<4><<<VB, TB>>>();

    // pooling (pool + upool fused) + final
    k_pool<<<PB + UPB, TB>>>(batch);
    k_final<<<NG, DC>>>(batch, fcb, out);
}